// round 2
// baseline (speedup 1.0000x reference)
#include <cuda_runtime.h>
#include <math.h>

// Problem constants
#define NB   4
#define HF   63              // Hf = Wf = 67 - 5 + 1
#define P    3969            // HF*HF
#define PPAD 3972            // pad to multiple of 4 floats (16B) for alignment
#define KF   75              // 3 * 5 * 5 features per patch
#define ROWS (NB * P)        // 15876
#define IN_H 67
#define W_SPATIAL 0.1f
#define SIGMA     0.5f
#define EPSV      1e-5f

#define F32_INF __int_as_float(0x7F800000)

// ---------------- scratch (static __device__ — no allocation in kernel_launch) ----------
__device__ float    g_I[NB * KF * PPAD];          // [n][k][p]  feature-major for GEMM
__device__ float    g_T[NB * KF * PPAD];
__device__ float    g_rI[ROWS];
__device__ float    g_rT[ROWS];
__device__ float    g_comb[(size_t)ROWS * PPAD];  // 252 MB
__device__ unsigned g_dmin[ROWS];
__device__ float    g_acc[NB];

// ---------------- init ------------------------------------------------------------------
__global__ void init_kernel() {
    int idx = blockIdx.x * blockDim.x + threadIdx.x;
    if (idx < ROWS) g_dmin[idx] = 0x7F800000u;  // +inf bits
    if (idx < NB)   g_acc[idx] = 0.0f;
}

// ---------------- patch extraction ------------------------------------------------------
// One thread per (which, n, k, p_pad). Writes feature-major [n][k][p], zero pad p>=P.
#define TOT1 (NB * KF * PPAD)
__global__ void feat_kernel(const float* __restrict__ outp, const float* __restrict__ targ) {
    int idx = blockIdx.x * blockDim.x + threadIdx.x;
    if (idx >= 2 * TOT1) return;
    int which = idx / TOT1;
    int rem   = idx - which * TOT1;
    int n     = rem / (KF * PPAD);
    int rem2  = rem - n * (KF * PPAD);
    int k     = rem2 / PPAD;
    int p     = rem2 - k * PPAD;

    float v = 0.0f;
    if (p < P) {
        int c  = k / 25;
        int t  = k - c * 25;
        int dy = t / 5;
        int dx = t - dy * 5;
        int y  = p / HF;
        int x  = p - y * HF;
        const float* src = which ? targ : outp;
        v = src[((n * 3 + c) * IN_H + (y + dy)) * IN_H + (x + dx)] - 0.5f;
    }
    float* dst = which ? g_T : g_I;
    dst[(n * KF + k) * PPAD + p] = v;
}

// ---------------- per-patch squared norms -----------------------------------------------
__global__ void rsq_kernel() {
    int idx = blockIdx.x * blockDim.x + threadIdx.x;
    if (idx >= 2 * ROWS) return;
    int which = idx / ROWS;
    int r     = idx - which * ROWS;
    int n     = r / P;
    int p     = r - n * P;
    const float* src = which ? g_T : g_I;
    float s = 0.0f;
    #pragma unroll 15
    for (int k = 0; k < KF; ++k) {
        float v = src[(n * KF + k) * PPAD + p];   // coalesced across threads
        s = fmaf(v, v, s);
    }
    float* dst = which ? g_rT : g_rI;
    dst[r] = s;
}

// ---------------- GEMM + comb + row-min -------------------------------------------------
// 64x64 tile, 256 threads, 4x4 microtile, K=75 in shared. Grid (63, 63, 4).
__global__ __launch_bounds__(256) void gemm_min_kernel() {
    __shared__ float As[KF][64];   // [k][i]
    __shared__ float Bs[KF][64];   // [k][j]

    int n  = blockIdx.z;
    int i0 = blockIdx.y * 64;
    int j0 = blockIdx.x * 64;
    int tid = threadIdx.x;

    for (int idx = tid; idx < KF * 64; idx += 256) {
        int k   = idx >> 6;
        int col = idx & 63;
        int gi = i0 + col;
        int gj = j0 + col;
        As[k][col] = (gi < P) ? g_I[(n * KF + k) * PPAD + gi] : 0.0f;
        Bs[k][col] = (gj < P) ? g_T[(n * KF + k) * PPAD + gj] : 0.0f;
    }
    __syncthreads();

    int tx = tid & 15;
    int ty = tid >> 4;

    float acc[4][4] = {};
    #pragma unroll 15
    for (int k = 0; k < KF; ++k) {
        float4 a = *(const float4*)(&As[k][ty << 2]);
        float4 b = *(const float4*)(&Bs[k][tx << 2]);
        acc[0][0] = fmaf(a.x, b.x, acc[0][0]);
        acc[0][1] = fmaf(a.x, b.y, acc[0][1]);
        acc[0][2] = fmaf(a.x, b.z, acc[0][2]);
        acc[0][3] = fmaf(a.x, b.w, acc[0][3]);
        acc[1][0] = fmaf(a.y, b.x, acc[1][0]);
        acc[1][1] = fmaf(a.y, b.y, acc[1][1]);
        acc[1][2] = fmaf(a.y, b.z, acc[1][2]);
        acc[1][3] = fmaf(a.y, b.w, acc[1][3]);
        acc[2][0] = fmaf(a.z, b.x, acc[2][0]);
        acc[2][1] = fmaf(a.z, b.y, acc[2][1]);
        acc[2][2] = fmaf(a.z, b.z, acc[2][2]);
        acc[2][3] = fmaf(a.z, b.w, acc[2][3]);
        acc[3][0] = fmaf(a.w, b.x, acc[3][0]);
        acc[3][1] = fmaf(a.w, b.y, acc[3][1]);
        acc[3][2] = fmaf(a.w, b.z, acc[3][2]);
        acc[3][3] = fmaf(a.w, b.w, acc[3][3]);
    }

    // Epilogue: comb = max(rI + rT - 2*dot, 0) + w_s * spatial; write + row min
    int ibase = i0 + (ty << 2);
    int jbase = j0 + (tx << 2);

    float rI[4], yi[4], xi[4];
    float rT[4], yj[4], xj[4];
    #pragma unroll
    for (int r = 0; r < 4; ++r) {
        int i = ibase + r;
        int iv = (i < P) ? i : 0;
        rI[r] = (i < P) ? g_rI[n * P + i] : 0.0f;
        int y = iv / HF, x = iv - y * HF;
        yi[r] = (float)y * (1.0f / (HF - 1));
        xi[r] = (float)x * (1.0f / (HF - 1));
    }
    #pragma unroll
    for (int c = 0; c < 4; ++c) {
        int j = jbase + c;
        int jv = (j < P) ? j : 0;
        rT[c] = (j < P) ? g_rT[n * P + j] : 0.0f;
        int y = jv / HF, x = jv - y * HF;
        yj[c] = (float)y * (1.0f / (HF - 1));
        xj[c] = (float)x * (1.0f / (HF - 1));
    }

    float rowmin[4] = {F32_INF, F32_INF, F32_INF, F32_INF};
    #pragma unroll
    for (int r = 0; r < 4; ++r) {
        int i = ibase + r;
        #pragma unroll
        for (int c = 0; c < 4; ++c) {
            int j = jbase + c;
            float d  = fmaxf(fmaf(-2.0f, acc[r][c], rI[r] + rT[c]), 0.0f);
            float dy = yi[r] - yj[c];
            float dx = xi[r] - xj[c];
            float comb = d + W_SPATIAL * (dy * dy + dx * dx);
            if (i < P && j < P) {
                g_comb[(size_t)(n * P + i) * PPAD + j] = comb;
                rowmin[r] = fminf(rowmin[r], comb);
            }
        }
    }

    // reduce row minima across the 16 tx lanes (xor offsets < 16 stay in the tx group)
    #pragma unroll
    for (int r = 0; r < 4; ++r) {
        float v = rowmin[r];
        #pragma unroll
        for (int off = 8; off >= 1; off >>= 1)
            v = fminf(v, __shfl_xor_sync(0xffffffffu, v, off));
        int i = ibase + r;
        if (tx == 0 && i < P)
            atomicMin(&g_dmin[n * P + i], __float_as_uint(v));  // comb >= 0 -> bit order ok
    }
}

// ---------------- fast exp (FMA pipe, avoids MUFU bottleneck) ---------------------------
__device__ __forceinline__ float fast_exp_neg(float x) {   // x <= 0
    float y = fmaxf(x * 1.4426950408889634f, -126.0f);
    float r = y + 12582912.0f;                 // round-to-nearest int
    int   e = __float_as_int(r) - 0x4B400000;  // e in [-126, 0]
    float f = y - (r - 12582912.0f);           // f in [-0.5, 0.5]
    float p = 1.3333558146e-3f;
    p = fmaf(p, f, 9.6181291918e-3f);
    p = fmaf(p, f, 5.5504108664e-2f);
    p = fmaf(p, f, 2.4022650695e-1f);
    p = fmaf(p, f, 6.9314718056e-1f);
    p = fmaf(p, f, 1.0f);
    return p * __int_as_float((e + 127) << 23);
}

// ---------------- per-row exp-sum -> k_max -> per-image accumulation --------------------
__global__ __launch_bounds__(256) void row_kernel() {
    int row = blockIdx.x;              // 0 .. ROWS-1
    int n   = row / P;
    float dmin = __uint_as_float(g_dmin[row]);
    float invs = 1.0f / (SIGMA * (dmin + EPSV));
    const float* crow = &g_comb[(size_t)row * PPAD];

    float sum = 0.0f;
    for (int j = threadIdx.x; j < P; j += 256) {
        float arg = (dmin - crow[j]) * invs;   // <= 0
        sum += fast_exp_neg(arg);
    }

    __shared__ float red[256];
    red[threadIdx.x] = sum;
    __syncthreads();
    for (int s = 128; s > 0; s >>= 1) {
        if (threadIdx.x < s) red[threadIdx.x] += red[threadIdx.x + s];
        __syncthreads();
    }
    if (threadIdx.x == 0)
        atomicAdd(&g_acc[n], 1.0f / red[0]);   // k_max for this row
}

// ---------------- final scalar ----------------------------------------------------------
__global__ void final_kernel(float* out) {
    float L = 0.0f;
    #pragma unroll
    for (int n = 0; n < NB; ++n)
        L += -logf(g_acc[n] * (1.0f / (float)P));
    out[0] = L;
}

// ---------------- launch ----------------------------------------------------------------
extern "C" void kernel_launch(void* const* d_in, const int* in_sizes, int n_in,
                              void* d_out, int out_size) {
    const float* outp = (const float*)d_in[0];
    const float* targ = (const float*)d_in[1];
    float* out = (float*)d_out;

    init_kernel<<<(ROWS + 255) / 256, 256>>>();
    feat_kernel<<<(2 * TOT1 + 255) / 256, 256>>>(outp, targ);
    rsq_kernel<<<(2 * ROWS + 255) / 256, 256>>>();
    dim3 g(63, 63, NB);
    gemm_min_kernel<<<g, 256>>>();
    row_kernel<<<ROWS, 256>>>();
    final_kernel<<<1, 1>>>(out);
}

// round 4
// speedup vs baseline: 1.8558x; 1.8558x over previous
#include <cuda_runtime.h>
#include <cuda_bf16.h>
#include <math.h>
#include <stdint.h>

// ---------------- problem constants ----------------
#define NB 4
#define HF 63
#define P  3969
#define RP 4096            // rows padded per image
#define KP 80              // 75 feats + 2 coord feats + 3 zero pad
#define NI 32
#define NJ 32
#define IN_H 67
#define CS  0.31622776601683794f   // sqrt(0.1)
#define L2E 1.4426950408889634f

// ---------------- scratch ----------------
__device__ __nv_bfloat16 g_hi[(size_t)2 * NB * RP * KP];
__device__ __nv_bfloat16 g_lo[(size_t)2 * NB * RP * KP];
__device__ float g_r[2 * NB * RP];
__device__ float g_acc[NB];

// ---------------- helpers ----------------
__device__ __forceinline__ uint32_t smem_u32(const void* p) {
    uint32_t a;
    asm("{ .reg .u64 t; cvta.to.shared.u64 t, %1; cvt.u32.u64 %0, t; }" : "=r"(a) : "l"(p));
    return a;
}
__device__ __forceinline__ void cp16(uint32_t dst, const void* src) {
    asm volatile("cp.async.cg.shared.global [%0], [%1], 16;" :: "r"(dst), "l"(src));
}
#define CP_COMMIT() asm volatile("cp.async.commit_group;" ::: "memory")
#define CP_WAIT0()  asm volatile("cp.async.wait_group 0;" ::: "memory")

__device__ __forceinline__ void ldsm4(uint32_t* r, uint32_t addr) {
    asm volatile("ldmatrix.sync.aligned.m8n8.x4.shared.b16 {%0,%1,%2,%3}, [%4];"
        : "=r"(r[0]), "=r"(r[1]), "=r"(r[2]), "=r"(r[3]) : "r"(addr));
}
__device__ __forceinline__ void mma16816(float* d, const uint32_t* a, uint32_t b0, uint32_t b1) {
    asm volatile("mma.sync.aligned.m16n8k16.row.col.f32.bf16.bf16.f32 "
        "{%0,%1,%2,%3},{%4,%5,%6,%7},{%8,%9},{%0,%1,%2,%3};"
        : "+f"(d[0]), "+f"(d[1]), "+f"(d[2]), "+f"(d[3])
        : "r"(a[0]), "r"(a[1]), "r"(a[2]), "r"(a[3]), "r"(b0), "r"(b1));
}
__device__ __forceinline__ float ex2f(float x) {
    float y; asm("ex2.approx.f32 %0, %1;" : "=f"(y) : "f"(x)); return y;
}

// ---------------- prep kernels ----------------
__global__ void init_kernel() { if (threadIdx.x < NB) g_acc[threadIdx.x] = 0.0f; }

__global__ void feat_kernel(const float* __restrict__ outp, const float* __restrict__ targ) {
    int idx = blockIdx.x * blockDim.x + threadIdx.x;
    const int TOT = 2 * NB * RP * KP;
    if (idx >= TOT) return;
    int k     = idx % KP;
    int row   = (idx / KP) % RP;
    int n     = (idx / (KP * RP)) % NB;
    int which = idx / (KP * RP * NB);
    float v = 0.0f;
    if (row < P) {
        int y = row / HF, x = row - y * HF;
        if (k < 75) {
            int c = k / 25, t = k - c * 25, dy = t / 5, dx = t - dy * 5;
            const float* src = which ? targ : outp;
            v = src[((n * 3 + c) * IN_H + y + dy) * IN_H + x + dx] - 0.5f;
        } else if (k == 75) v = CS * (float)y * (1.0f / 62.0f);
        else if (k == 76)   v = CS * (float)x * (1.0f / 62.0f);
    }
    __nv_bfloat16 h = __float2bfloat16(v);
    float lo = v - __bfloat162float(h);
    g_hi[idx] = h;
    g_lo[idx] = __float2bfloat16(lo);
}

__global__ void rsq_kernel() {
    int idx = blockIdx.x * blockDim.x + threadIdx.x;
    if (idx >= 2 * NB * RP) return;
    int row   = idx % RP;
    int which = idx / (NB * RP);
    size_t base = (size_t)idx * KP;
    float s = 0.0f;
    #pragma unroll 16
    for (int k = 0; k < KP; ++k) {
        float v = __bfloat162float(g_hi[base + k]) + __bfloat162float(g_lo[base + k]);
        s = fmaf(v, v, s);
    }
    if (which == 1 && row >= P) s = 1e9f;   // T pad rows: huge dist -> exp ~0, min unaffected
    g_r[idx] = s;
}

// ---------------- main fused kernel ----------------
#define TS     176                 // smem row stride (bytes) -> ldmatrix conflict-free
#define TILE_B (128 * TS)          // 22528 per (hi or lo) tile
#define SM_RI  0
#define SM_RT  512                 // 2 x 128 floats (double buffered)
#define SM_MS  1536
#define SM_BS  2048
#define SM_RED 2560                // int row-min
#define SM_SUM 3072                // float row-sum
#define SM_AH  4096
#define SM_AL  (SM_AH + TILE_B)
#define SM_B0  (SM_AL + TILE_B)    // 49152
#define BUF_B  (2 * TILE_B)        // hi+lo per stage = 45056
#define SMEM_BYTES (SM_B0 + 2 * BUF_B)   // 139264

__device__ __forceinline__ void load_B_async(uint32_t smB,
                                             const __nv_bfloat16* __restrict__ hi,
                                             const __nv_bfloat16* __restrict__ lo, int tid) {
    for (int t = tid; t < 1280; t += 512) {
        int row = t / 10, c = t - row * 10;
        uint32_t d = smB + row * TS + c * 16;
        cp16(d,          hi + row * KP + c * 8);
        cp16(d + TILE_B, lo + row * KP + c * 8);
    }
}

__global__ __launch_bounds__(512, 1) void main_kernel() {
    extern __shared__ char sm[];
    uint32_t smb = smem_u32(sm);
    int tid = threadIdx.x;
    int w = tid >> 5, l = tid & 31;
    int n  = blockIdx.y;
    int i0 = blockIdx.x * 128;
    int wm = w >> 2, wn = w & 3;

    float* rI_s  = (float*)(sm + SM_RI);
    float* rT_s  = (float*)(sm + SM_RT);
    float* m_s   = (float*)(sm + SM_MS);
    float* b_s   = (float*)(sm + SM_BS);
    int*   red_s = (int*)  (sm + SM_RED);
    float* sum_s = (float*)(sm + SM_SUM);

    // ---- load A tile (once) + rI + init reductions ----
    const __nv_bfloat16* Ahi = g_hi + ((size_t)n * RP + i0) * KP;
    const __nv_bfloat16* Alo = g_lo + ((size_t)n * RP + i0) * KP;
    for (int t = tid; t < 1280; t += 512) {
        int row = t / 10, c = t - row * 10;
        uint4 vh = *(const uint4*)(Ahi + row * KP + c * 8);
        uint4 vl = *(const uint4*)(Alo + row * KP + c * 8);
        *(uint4*)(sm + SM_AH + row * TS + c * 16) = vh;
        *(uint4*)(sm + SM_AL + row * TS + c * 16) = vl;
    }
    if (tid < 128) {
        rI_s[tid]  = g_r[n * RP + i0 + tid];
        red_s[tid] = 0x7F7FFFFF;   // FLT_MAX
        sum_s[tid] = 0.0f;
    }
    __syncthreads();

    // ---- per-lane geometry ----
    int qr = l >> 2;            // row within 8 (C frag)
    int qc = (l & 3) * 2;       // col pair base (C frag)
    int lrow = (l & 7) + ((l >> 3) & 1) * 8;    // ldmatrix row pattern
    int lcol = (l >> 4) * 16;                   // ldmatrix 16B col pattern
    int aoff = (wm * 32 + lrow) * TS + lcol;
    int boff = (wn * 32 + lrow) * TS + lcol;

    float ri[2][2];
    #pragma unroll
    for (int mt = 0; mt < 2; ++mt)
        #pragma unroll
        for (int h = 0; h < 2; ++h)
            ri[mt][h] = rI_s[wm * 32 + mt * 16 + qr + h * 8];

    const __nv_bfloat16* Bhi0 = g_hi + (size_t)(NB + n) * RP * KP;
    const __nv_bfloat16* Blo0 = g_lo + (size_t)(NB + n) * RP * KP;
    const float* rTg = g_r + (NB + n) * RP;

    float mcoef[2][2], bcoef[2][2];
    float rmin[2][2] = {{1e30f, 1e30f}, {1e30f, 1e30f}};
    float ssum[2][2] = {{0.f, 0.f}, {0.f, 0.f}};

    for (int pass = 0; pass < 2; ++pass) {
        // preload j=0
        load_B_async(smb + SM_B0, Bhi0, Blo0, tid);
        CP_COMMIT();
        if (tid < 128) rT_s[tid] = rTg[tid];

        for (int j = 0; j < NJ; ++j) {
            int cur = j & 1;
            CP_WAIT0();
            __syncthreads();
            if (j + 1 < NJ) {
                load_B_async(smb + SM_B0 + (cur ^ 1) * BUF_B,
                             Bhi0 + (size_t)(j + 1) * 128 * KP,
                             Blo0 + (size_t)(j + 1) * 128 * KP, tid);
                CP_COMMIT();
                if (tid < 128) rT_s[(cur ^ 1) * 128 + tid] = rTg[(j + 1) * 128 + tid];
            }

            // ---- GEMM: D = A . B^T for this 128x128 tile (3-way split bf16) ----
            float acc[2][4][4];
            #pragma unroll
            for (int mt = 0; mt < 2; ++mt)
                #pragma unroll
                for (int nt = 0; nt < 4; ++nt)
                    #pragma unroll
                    for (int q = 0; q < 4; ++q) acc[mt][nt][q] = 0.0f;

            uint32_t Bcur = smb + SM_B0 + cur * BUF_B;
            #pragma unroll
            for (int s = 0; s < 3; ++s) {
                uint32_t Abase = (s == 2) ? (smb + SM_AL) : (smb + SM_AH);
                uint32_t Bbase = (s == 1) ? (Bcur + TILE_B) : Bcur;
                #pragma unroll
                for (int kk = 0; kk < 5; ++kk) {
                    uint32_t A0[4], A1[4], B0[4], B1[4];
                    ldsm4(A0, Abase + aoff + kk * 32);
                    ldsm4(A1, Abase + aoff + 16 * TS + kk * 32);
                    ldsm4(B0, Bbase + boff + kk * 32);
                    ldsm4(B1, Bbase + boff + 16 * TS + kk * 32);
                    mma16816(acc[0][0], A0, B0[0], B0[2]);
                    mma16816(acc[0][1], A0, B0[1], B0[3]);
                    mma16816(acc[0][2], A0, B1[0], B1[2]);
                    mma16816(acc[0][3], A0, B1[1], B1[3]);
                    mma16816(acc[1][0], A1, B0[0], B0[2]);
                    mma16816(acc[1][1], A1, B0[1], B0[3]);
                    mma16816(acc[1][2], A1, B1[0], B1[2]);
                    mma16816(acc[1][3], A1, B1[1], B1[3]);
                }
            }

            // ---- epilogue on register fragments ----
            float rt[4][2];
            #pragma unroll
            for (int nt = 0; nt < 4; ++nt) {
                rt[nt][0] = rT_s[cur * 128 + wn * 32 + nt * 8 + qc];
                rt[nt][1] = rT_s[cur * 128 + wn * 32 + nt * 8 + qc + 1];
            }
            if (pass == 0) {
                #pragma unroll
                for (int mt = 0; mt < 2; ++mt)
                    #pragma unroll
                    for (int nt = 0; nt < 4; ++nt)
                        #pragma unroll
                        for (int q = 0; q < 4; ++q) {
                            int h = q >> 1, pq = q & 1;
                            float comb = fmaxf(fmaf(-2.0f, acc[mt][nt][q],
                                                    ri[mt][h] + rt[nt][pq]), 0.0f);
                            rmin[mt][h] = fminf(rmin[mt][h], comb);
                        }
            } else {
                #pragma unroll
                for (int mt = 0; mt < 2; ++mt)
                    #pragma unroll
                    for (int nt = 0; nt < 4; ++nt)
                        #pragma unroll
                        for (int q = 0; q < 4; ++q) {
                            int h = q >> 1, pq = q & 1;
                            float comb = fmaxf(fmaf(-2.0f, acc[mt][nt][q],
                                                    ri[mt][h] + rt[nt][pq]), 0.0f);
                            ssum[mt][h] += ex2f(fmaf(comb, mcoef[mt][h], bcoef[mt][h]));
                        }
            }
        }

        if (pass == 0) {
            // reduce row minima: quad (cols) -> shared
            #pragma unroll
            for (int mt = 0; mt < 2; ++mt)
                #pragma unroll
                for (int h = 0; h < 2; ++h) {
                    float v = rmin[mt][h];
                    v = fminf(v, __shfl_xor_sync(0xffffffffu, v, 1));
                    v = fminf(v, __shfl_xor_sync(0xffffffffu, v, 2));
                    if ((l & 3) == 0)
                        atomicMin(&red_s[wm * 32 + mt * 16 + qr + h * 8], __float_as_int(v));
                }
            __syncthreads();
            if (tid < 128) {
                float dmin = __int_as_float(red_s[tid]);
                float m = -L2E / (0.5f * (dmin + 1e-5f));
                m_s[tid] = m;
                b_s[tid] = -dmin * m;
            }
            __syncthreads();
            #pragma unroll
            for (int mt = 0; mt < 2; ++mt)
                #pragma unroll
                for (int h = 0; h < 2; ++h) {
                    int row = wm * 32 + mt * 16 + qr + h * 8;
                    mcoef[mt][h] = m_s[row];
                    bcoef[mt][h] = b_s[row];
                }
        }
    }

    // ---- row sums -> k_max -> per-image accumulation ----
    #pragma unroll
    for (int mt = 0; mt < 2; ++mt)
        #pragma unroll
        for (int h = 0; h < 2; ++h) {
            float v = ssum[mt][h];
            v += __shfl_xor_sync(0xffffffffu, v, 1);
            v += __shfl_xor_sync(0xffffffffu, v, 2);
            if ((l & 3) == 0)
                atomicAdd(&sum_s[wm * 32 + mt * 16 + qr + h * 8], v);
        }
    __syncthreads();
    if (tid < 128)
        rI_s[tid] = (i0 + tid < P) ? (1.0f / sum_s[tid]) : 0.0f;
    __syncthreads();
    for (int s = 64; s > 0; s >>= 1) {
        if (tid < s) rI_s[tid] += rI_s[tid + s];
        __syncthreads();
    }
    if (tid == 0) atomicAdd(&g_acc[n], rI_s[0]);
}

// ---------------- final scalar ----------------
__global__ void final_kernel(float* out) {
    float L = 0.0f;
    #pragma unroll
    for (int n = 0; n < NB; ++n)
        L += -logf(g_acc[n] * (1.0f / (float)P));
    out[0] = L;
}

// ---------------- launch ----------------
extern "C" void kernel_launch(void* const* d_in, const int* in_sizes, int n_in,
                              void* d_out, int out_size) {
    const float* outp = (const float*)d_in[0];
    const float* targ = (const float*)d_in[1];
    float* out = (float*)d_out;

    cudaFuncSetAttribute(main_kernel, cudaFuncAttributeMaxDynamicSharedMemorySize, SMEM_BYTES);

    init_kernel<<<1, 32>>>();
    const int TOT = 2 * NB * RP * KP;
    feat_kernel<<<(TOT + 255) / 256, 256>>>(outp, targ);
    rsq_kernel<<<(2 * NB * RP + 255) / 256, 256>>>();
    main_kernel<<<dim3(NI, NB), 512, SMEM_BYTES>>>();
    final_kernel<<<1, 1>>>(out);
}

// round 6
// speedup vs baseline: 2.7713x; 1.4933x over previous
#include <cuda_runtime.h>
#include <cuda_bf16.h>
#include <cuda_fp16.h>
#include <math.h>
#include <stdint.h>

// ---------------- problem constants ----------------
#define NB 4
#define HF 63
#define P  3969
#define RP 4096            // rows padded per image
#define KP 80              // 75 feats + 2 coord feats + 3 zero pad
#define NI 32
#define NJ 32
#define IN_H 67
#define CS  0.31622776601683794f   // sqrt(0.1)
#define L2E 1.4426950408889634f

// ---------------- scratch ----------------
__device__ __nv_bfloat16 g_hi[(size_t)2 * NB * RP * KP];
__device__ __nv_bfloat16 g_lo[(size_t)2 * NB * RP * KP];
__device__ float g_r[2 * NB * RP];
__device__ float g_m[NB * RP];
__device__ float g_b[NB * RP];
__device__ __half g_comb[(size_t)NB * RP * RP];   // 134 MB
__device__ float g_acc[NB];

// ---------------- helpers ----------------
__device__ __forceinline__ uint32_t smem_u32(const void* p) {
    uint32_t a;
    asm("{ .reg .u64 t; cvta.to.shared.u64 t, %1; cvt.u32.u64 %0, t; }" : "=r"(a) : "l"(p));
    return a;
}
__device__ __forceinline__ void cp16(uint32_t dst, const void* src) {
    asm volatile("cp.async.cg.shared.global [%0], [%1], 16;" :: "r"(dst), "l"(src));
}
#define CP_COMMIT() asm volatile("cp.async.commit_group;" ::: "memory")
#define CP_WAIT0()  asm volatile("cp.async.wait_group 0;" ::: "memory")

__device__ __forceinline__ void ldsm4(uint32_t* r, uint32_t addr) {
    asm volatile("ldmatrix.sync.aligned.m8n8.x4.shared.b16 {%0,%1,%2,%3}, [%4];"
        : "=r"(r[0]), "=r"(r[1]), "=r"(r[2]), "=r"(r[3]) : "r"(addr));
}
__device__ __forceinline__ void mma16816(float* d, const uint32_t* a, uint32_t b0, uint32_t b1) {
    asm volatile("mma.sync.aligned.m16n8k16.row.col.f32.bf16.bf16.f32 "
        "{%0,%1,%2,%3},{%4,%5,%6,%7},{%8,%9},{%0,%1,%2,%3};"
        : "+f"(d[0]), "+f"(d[1]), "+f"(d[2]), "+f"(d[3])
        : "r"(a[0]), "r"(a[1]), "r"(a[2]), "r"(a[3]), "r"(b0), "r"(b1));
}
__device__ __forceinline__ float ex2f(float x) {
    float y; asm("ex2.approx.f32 %0, %1;" : "=f"(y) : "f"(x)); return y;
}
__device__ __forceinline__ uint32_t pack_f16x2(float lo, float hi) {
    uint32_t u;
    asm("cvt.rn.f16x2.f32 %0, %1, %2;" : "=r"(u) : "f"(hi), "f"(lo));
    return u;
}

// ---------------- prep kernels ----------------
__global__ void init_kernel() { if (threadIdx.x < NB) g_acc[threadIdx.x] = 0.0f; }

__global__ void feat_kernel(const float* __restrict__ outp, const float* __restrict__ targ) {
    int idx = blockIdx.x * blockDim.x + threadIdx.x;
    const int TOT = 2 * NB * RP * KP;
    if (idx >= TOT) return;
    int k     = idx % KP;
    int row   = (idx / KP) % RP;
    int n     = (idx / (KP * RP)) % NB;
    int which = idx / (KP * RP * NB);
    float v = 0.0f;
    if (row < P) {
        int y = row / HF, x = row - y * HF;
        if (k < 75) {
            int c = k / 25, t = k - c * 25, dy = t / 5, dx = t - dy * 5;
            const float* src = which ? targ : outp;
            v = src[((n * 3 + c) * IN_H + y + dy) * IN_H + x + dx] - 0.5f;
        } else if (k == 75) v = CS * (float)y * (1.0f / 62.0f);
        else if (k == 76)   v = CS * (float)x * (1.0f / 62.0f);
    }
    __nv_bfloat16 h = __float2bfloat16(v);
    float lo = v - __bfloat162float(h);
    g_hi[idx] = h;
    g_lo[idx] = __float2bfloat16(lo);
}

__global__ void rsq_kernel() {
    int idx = blockIdx.x * blockDim.x + threadIdx.x;
    if (idx >= 2 * NB * RP) return;
    int row   = idx % RP;
    int which = idx / (NB * RP);
    size_t base = (size_t)idx * KP;
    float s = 0.0f;
    #pragma unroll 16
    for (int k = 0; k < KP; ++k) {
        float v = __bfloat162float(g_hi[base + k]) + __bfloat162float(g_lo[base + k]);
        s = fmaf(v, v, s);
    }
    if (which == 1 && row >= P) s = 1e9f;   // T pad rows: comb huge -> fp16 inf -> exp 0
    g_r[idx] = s;
}

// ---------------- main GEMM kernel ----------------
#define TS     176                 // smem row stride (bytes), ldmatrix conflict-free
#define TILE_B (128 * TS)          // 22528
#define SM_RT  0                   // 2 x 128 f
#define SM_RI  1024
#define SM_RED 1536                // int row-min
#define SM_AH  4096
#define SM_AL  (SM_AH + TILE_B)
#define SM_B0  (SM_AL + TILE_B)    // 49152
#define BUF_B  (2 * TILE_B)        // hi+lo per stage
#define SM_STG (SM_B0 + 2 * BUF_B) // 139264
#define STG_S  272                 // stage row stride bytes (68 words -> conflict-free)
#define SMEM_BYTES (SM_STG + 128 * STG_S)   // 174080

__device__ __forceinline__ void load_B_async(uint32_t smB,
                                             const __nv_bfloat16* __restrict__ hi,
                                             const __nv_bfloat16* __restrict__ lo, int tid) {
    for (int t = tid; t < 1280; t += 512) {
        int row = t / 10, c = t - row * 10;
        uint32_t d = smB + row * TS + c * 16;
        cp16(d,          hi + row * KP + c * 8);
        cp16(d + TILE_B, lo + row * KP + c * 8);
    }
}

__global__ __launch_bounds__(512, 1) void main_kernel() {
    extern __shared__ char sm[];
    uint32_t smb = smem_u32(sm);
    int tid = threadIdx.x;
    int w = tid >> 5, l = tid & 31;
    int n  = blockIdx.y;
    int i0 = blockIdx.x * 128;
    int wm = w >> 2, wn = w & 3;

    float* rT_s  = (float*)(sm + SM_RT);
    float* rI_s  = (float*)(sm + SM_RI);
    int*   red_s = (int*)  (sm + SM_RED);

    // ---- load A tile (once) + rI + init min ----
    const __nv_bfloat16* Ahi = g_hi + ((size_t)n * RP + i0) * KP;
    const __nv_bfloat16* Alo = g_lo + ((size_t)n * RP + i0) * KP;
    for (int t = tid; t < 1280; t += 512) {
        int row = t / 10, c = t - row * 10;
        *(uint4*)(sm + SM_AH + row * TS + c * 16) = *(const uint4*)(Ahi + row * KP + c * 8);
        *(uint4*)(sm + SM_AL + row * TS + c * 16) = *(const uint4*)(Alo + row * KP + c * 8);
    }
    if (tid < 128) {
        rI_s[tid]  = g_r[n * RP + i0 + tid];
        red_s[tid] = 0x7F7FFFFF;   // FLT_MAX
    }
    __syncthreads();

    // ---- per-lane geometry ----
    int qr = l >> 2;
    int qc = (l & 3) * 2;
    int lrow = (l & 7) + ((l >> 3) & 1) * 8;
    int lcol = (l >> 4) * 16;
    int aoff = (wm * 32 + lrow) * TS + lcol;
    int boff = (wn * 32 + lrow) * TS + lcol;

    float ri[2][2];
    #pragma unroll
    for (int mt = 0; mt < 2; ++mt)
        #pragma unroll
        for (int h = 0; h < 2; ++h)
            ri[mt][h] = rI_s[wm * 32 + mt * 16 + qr + h * 8];

    const __nv_bfloat16* Bhi0 = g_hi + (size_t)(NB + n) * RP * KP;
    const __nv_bfloat16* Blo0 = g_lo + (size_t)(NB + n) * RP * KP;
    const float* rTg = g_r + (NB + n) * RP;

    float rmin[2][2] = {{1e30f, 1e30f}, {1e30f, 1e30f}};
    unsigned* gout = (unsigned*)g_comb;
    size_t rowbase = ((size_t)n * RP + i0) * RP;   // in halfs

    // preload j=0
    load_B_async(smb + SM_B0, Bhi0, Blo0, tid);
    CP_COMMIT();
    if (tid < 128) rT_s[tid] = rTg[tid];

    for (int j = 0; j < NJ; ++j) {
        int cur = j & 1;
        CP_WAIT0();
        __syncthreads();               // B[cur] ready; stage free (copied last iter)
        if (j + 1 < NJ) {
            load_B_async(smb + SM_B0 + (cur ^ 1) * BUF_B,
                         Bhi0 + (size_t)(j + 1) * 128 * KP,
                         Blo0 + (size_t)(j + 1) * 128 * KP, tid);
            CP_COMMIT();
            if (tid < 128) rT_s[(cur ^ 1) * 128 + tid] = rTg[(j + 1) * 128 + tid];
        }

        // ---- GEMM: 3-way split bf16 with A-hi/B-hi fragment reuse ----
        float acc[2][4][4];
        #pragma unroll
        for (int mt = 0; mt < 2; ++mt)
            #pragma unroll
            for (int nt = 0; nt < 4; ++nt)
                #pragma unroll
                for (int q = 0; q < 4; ++q) acc[mt][nt][q] = 0.0f;

        uint32_t Bcur = smb + SM_B0 + cur * BUF_B;
        #pragma unroll
        for (int kk = 0; kk < 5; ++kk) {
            uint32_t AH0[4], AH1[4], AL0[4], AL1[4], BH0[4], BH1[4], BL0[4], BL1[4];
            ldsm4(BH0, Bcur + boff + kk * 32);
            ldsm4(BH1, Bcur + boff + 16 * TS + kk * 32);
            ldsm4(AH0, smb + SM_AH + aoff + kk * 32);
            ldsm4(AH1, smb + SM_AH + aoff + 16 * TS + kk * 32);
            // hh
            mma16816(acc[0][0], AH0, BH0[0], BH0[2]);
            mma16816(acc[0][1], AH0, BH0[1], BH0[3]);
            mma16816(acc[0][2], AH0, BH1[0], BH1[2]);
            mma16816(acc[0][3], AH0, BH1[1], BH1[3]);
            mma16816(acc[1][0], AH1, BH0[0], BH0[2]);
            mma16816(acc[1][1], AH1, BH0[1], BH0[3]);
            mma16816(acc[1][2], AH1, BH1[0], BH1[2]);
            mma16816(acc[1][3], AH1, BH1[1], BH1[3]);
            // lh (reuse BH)
            ldsm4(AL0, smb + SM_AL + aoff + kk * 32);
            ldsm4(AL1, smb + SM_AL + aoff + 16 * TS + kk * 32);
            mma16816(acc[0][0], AL0, BH0[0], BH0[2]);
            mma16816(acc[0][1], AL0, BH0[1], BH0[3]);
            mma16816(acc[0][2], AL0, BH1[0], BH1[2]);
            mma16816(acc[0][3], AL0, BH1[1], BH1[3]);
            mma16816(acc[1][0], AL1, BH0[0], BH0[2]);
            mma16816(acc[1][1], AL1, BH0[1], BH0[3]);
            mma16816(acc[1][2], AL1, BH1[0], BH1[2]);
            mma16816(acc[1][3], AL1, BH1[1], BH1[3]);
            // hl (reuse AH)
            ldsm4(BL0, Bcur + TILE_B + boff + kk * 32);
            ldsm4(BL1, Bcur + TILE_B + boff + 16 * TS + kk * 32);
            mma16816(acc[0][0], AH0, BL0[0], BL0[2]);
            mma16816(acc[0][1], AH0, BL0[1], BL0[3]);
            mma16816(acc[0][2], AH0, BL1[0], BL1[2]);
            mma16816(acc[0][3], AH0, BL1[1], BL1[3]);
            mma16816(acc[1][0], AH1, BL0[0], BL0[2]);
            mma16816(acc[1][1], AH1, BL0[1], BL0[3]);
            mma16816(acc[1][2], AH1, BL1[0], BL1[2]);
            mma16816(acc[1][3], AH1, BL1[1], BL1[3]);
        }

        // ---- epilogue: comb, row-min, stage fp16 ----
        float rt[4][2];
        #pragma unroll
        for (int nt = 0; nt < 4; ++nt) {
            rt[nt][0] = rT_s[cur * 128 + wn * 32 + nt * 8 + qc];
            rt[nt][1] = rT_s[cur * 128 + wn * 32 + nt * 8 + qc + 1];
        }
        #pragma unroll
        for (int mt = 0; mt < 2; ++mt)
            #pragma unroll
            for (int nt = 0; nt < 4; ++nt)
                #pragma unroll
                for (int h = 0; h < 2; ++h) {
                    float c0 = fmaxf(fmaf(-2.0f, acc[mt][nt][2*h],   ri[mt][h] + rt[nt][0]), 0.0f);
                    float c1 = fmaxf(fmaf(-2.0f, acc[mt][nt][2*h+1], ri[mt][h] + rt[nt][1]), 0.0f);
                    rmin[mt][h] = fminf(rmin[mt][h], fminf(c0, c1));
                    int srow = wm * 32 + mt * 16 + h * 8 + qr;
                    int scol = wn * 32 + nt * 8 + qc;
                    *(uint32_t*)(sm + SM_STG + srow * STG_S + scol * 2) = pack_f16x2(c0, c1);
                }
        __syncthreads();               // stage fully written

        // ---- coalesced copy-out (32KB) ----
        {
            const unsigned* stg = (const unsigned*)(sm + SM_STG);
            #pragma unroll
            for (int it = 0; it < 16; ++it) {
                int wd  = tid + it * 512;      // 8192 words
                int row = wd >> 6, wp = wd & 63;
                gout[(rowbase + (size_t)row * RP + j * 128) / 2 + wp] =
                    stg[row * (STG_S / 4) + wp];
            }
        }
    }

    // ---- row minima -> per-row exp coefficients ----
    #pragma unroll
    for (int mt = 0; mt < 2; ++mt)
        #pragma unroll
        for (int h = 0; h < 2; ++h) {
            float v = rmin[mt][h];
            v = fminf(v, __shfl_xor_sync(0xffffffffu, v, 1));
            v = fminf(v, __shfl_xor_sync(0xffffffffu, v, 2));
            if ((l & 3) == 0)
                atomicMin(&red_s[wm * 32 + mt * 16 + qr + h * 8], __float_as_int(v));
        }
    __syncthreads();
    if (tid < 128) {
        float dmin = __int_as_float(red_s[tid]);
        float m = -L2E / (0.5f * (dmin + 1e-5f));
        g_m[n * RP + i0 + tid] = m;
        g_b[n * RP + i0 + tid] = -dmin * m;
    }
}

// ---------------- per-row exp-sum kernel (memory-bound) ----------------
__global__ __launch_bounds__(128) void row_kernel() {
    int n = blockIdx.y;
    int r = n * RP + blockIdx.x;          // blockIdx.x < P
    float m = g_m[r], b = g_b[r];
    const uint4* p = (const uint4*)(g_comb + (size_t)r * RP);

    float s = 0.0f;
    #pragma unroll
    for (int it = 0; it < 4; ++it) {
        uint4 v = p[threadIdx.x + it * 128];
        #pragma unroll
        for (int q = 0; q < 4; ++q) {
            unsigned u = (&v.x)[q];
            float2 f = __half22float2(*(__half2*)&u);
            s += ex2f(fmaf(f.x, m, b));
            s += ex2f(fmaf(f.y, m, b));
        }
    }
    // block reduce
    #pragma unroll
    for (int off = 16; off >= 1; off >>= 1)
        s += __shfl_xor_sync(0xffffffffu, s, off);
    __shared__ float red[4];
    if ((threadIdx.x & 31) == 0) red[threadIdx.x >> 5] = s;
    __syncthreads();
    if (threadIdx.x == 0) {
        float t = red[0] + red[1] + red[2] + red[3];
        atomicAdd(&g_acc[n], 1.0f / t);
    }
}

// ---------------- final scalar ----------------
__global__ void final_kernel(float* out) {
    float L = 0.0f;
    #pragma unroll
    for (int n = 0; n < NB; ++n)
        L += -logf(g_acc[n] * (1.0f / (float)P));
    out[0] = L;
}

// ---------------- launch ----------------
extern "C" void kernel_launch(void* const* d_in, const int* in_sizes, int n_in,
                              void* d_out, int out_size) {
    const float* outp = (const float*)d_in[0];
    const float* targ = (const float*)d_in[1];
    float* out = (float*)d_out;

    cudaFuncSetAttribute(main_kernel, cudaFuncAttributeMaxDynamicSharedMemorySize, SMEM_BYTES);

    init_kernel<<<1, 32>>>();
    const int TOT = 2 * NB * RP * KP;
    feat_kernel<<<(TOT + 255) / 256, 256>>>(outp, targ);
    rsq_kernel<<<(2 * NB * RP + 255) / 256, 256>>>();
    main_kernel<<<dim3(NI, NB), 512, SMEM_BYTES>>>();
    row_kernel<<<dim3(P, NB), 128>>>();
    final_kernel<<<1, 1>>>(out);
}

// round 7
// speedup vs baseline: 2.8314x; 1.0217x over previous
#include <cuda_runtime.h>
#include <cuda_bf16.h>
#include <cuda_fp16.h>
#include <math.h>
#include <stdint.h>

// ---------------- problem constants ----------------
#define NB 4
#define HF 63
#define P  3969
#define RP 4096            // rows padded per image
#define KP 80              // 75 feats + 2 coord feats + 3 zero pad
#define NI 32
#define NJ 32
#define IN_H 67
#define CS  0.31622776601683794f   // sqrt(0.1)
#define L2E 1.4426950408889634f

// ---------------- scratch ----------------
__device__ __nv_bfloat16 g_hi[(size_t)2 * NB * RP * KP];
__device__ __nv_bfloat16 g_lo[(size_t)2 * NB * RP * KP];
__device__ float g_r[2 * NB * RP];
__device__ float g_m[NB * RP];
__device__ float g_b[NB * RP];
__device__ __half g_comb[(size_t)NB * RP * RP];   // 134 MB
__device__ float g_acc[NB];

// ---------------- helpers ----------------
__device__ __forceinline__ uint32_t smem_u32(const void* p) {
    uint32_t a;
    asm("{ .reg .u64 t; cvta.to.shared.u64 t, %1; cvt.u32.u64 %0, t; }" : "=r"(a) : "l"(p));
    return a;
}
__device__ __forceinline__ void cp16(uint32_t dst, const void* src) {
    asm volatile("cp.async.cg.shared.global [%0], [%1], 16;" :: "r"(dst), "l"(src));
}
#define CP_COMMIT() asm volatile("cp.async.commit_group;" ::: "memory")
#define CP_WAIT0()  asm volatile("cp.async.wait_group 0;" ::: "memory")

__device__ __forceinline__ void ldsm4(uint32_t* r, uint32_t addr) {
    asm volatile("ldmatrix.sync.aligned.m8n8.x4.shared.b16 {%0,%1,%2,%3}, [%4];"
        : "=r"(r[0]), "=r"(r[1]), "=r"(r[2]), "=r"(r[3]) : "r"(addr));
}
__device__ __forceinline__ void mma16816(float* d, const uint32_t* a, uint32_t b0, uint32_t b1) {
    asm volatile("mma.sync.aligned.m16n8k16.row.col.f32.bf16.bf16.f32 "
        "{%0,%1,%2,%3},{%4,%5,%6,%7},{%8,%9},{%0,%1,%2,%3};"
        : "+f"(d[0]), "+f"(d[1]), "+f"(d[2]), "+f"(d[3])
        : "r"(a[0]), "r"(a[1]), "r"(a[2]), "r"(a[3]), "r"(b0), "r"(b1));
}
__device__ __forceinline__ float ex2f(float x) {
    float y; asm("ex2.approx.f32 %0, %1;" : "=f"(y) : "f"(x)); return y;
}
__device__ __forceinline__ uint32_t pack_f16x2(float lo, float hi) {
    uint32_t u;
    asm("cvt.rn.f16x2.f32 %0, %1, %2;" : "=r"(u) : "f"(hi), "f"(lo));
    return u;
}

// ---------------- prep kernels ----------------
__global__ void init_kernel() { if (threadIdx.x < NB) g_acc[threadIdx.x] = 0.0f; }

__global__ void feat_kernel(const float* __restrict__ outp, const float* __restrict__ targ) {
    int idx = blockIdx.x * blockDim.x + threadIdx.x;
    const int TOT = 2 * NB * RP * KP;
    if (idx >= TOT) return;
    int k     = idx % KP;
    int row   = (idx / KP) % RP;
    int n     = (idx / (KP * RP)) % NB;
    int which = idx / (KP * RP * NB);
    float v = 0.0f;
    if (row < P) {
        int y = row / HF, x = row - y * HF;
        if (k < 75) {
            int c = k / 25, t = k - c * 25, dy = t / 5, dx = t - dy * 5;
            const float* src = which ? targ : outp;
            v = src[((n * 3 + c) * IN_H + y + dy) * IN_H + x + dx] - 0.5f;
        } else if (k == 75) v = CS * (float)y * (1.0f / 62.0f);
        else if (k == 76)   v = CS * (float)x * (1.0f / 62.0f);
    }
    __nv_bfloat16 h = __float2bfloat16(v);
    float lo = v - __bfloat162float(h);
    g_hi[idx] = h;
    g_lo[idx] = __float2bfloat16(lo);
}

__global__ void rsq_kernel() {
    int idx = blockIdx.x * blockDim.x + threadIdx.x;
    if (idx >= 2 * NB * RP) return;
    int row   = idx % RP;
    int which = idx / (NB * RP);
    size_t base = (size_t)idx * KP;
    float s = 0.0f;
    #pragma unroll 16
    for (int k = 0; k < KP; ++k) {
        float v = __bfloat162float(g_hi[base + k]) + __bfloat162float(g_lo[base + k]);
        s = fmaf(v, v, s);
    }
    if (which == 1 && row >= P) s = 1e9f;   // T pad rows: comb huge -> fp16 inf -> exp 0
    g_r[idx] = s;
}

// ---------------- main GEMM kernel ----------------
#define TS     176                 // smem row stride (bytes), ldmatrix conflict-free
#define TILE_B (128 * TS)          // 22528
#define SM_RT  0                   // 2 x 128 f
#define SM_RI  1024
#define SM_RED 1536                // int row-min
#define SM_AH  4096
#define SM_AL  (SM_AH + TILE_B)
#define SM_B0  (SM_AL + TILE_B)    // 49152
#define BUF_B  (2 * TILE_B)        // hi+lo per stage
#define SM_STG (SM_B0 + 2 * BUF_B) // 139264
#define STG_S  272                 // stage row stride bytes (68 words -> conflict-free)
#define STG_BUF (128 * STG_S)      // 34816 per stage buffer
#define SMEM_BYTES (SM_STG + 2 * STG_BUF)   // 208896

__device__ __forceinline__ void load_B_async(uint32_t smB,
                                             const __nv_bfloat16* __restrict__ hi,
                                             const __nv_bfloat16* __restrict__ lo, int tid) {
    for (int t = tid; t < 1280; t += 512) {
        int row = t / 10, c = t - row * 10;
        uint32_t d = smB + row * TS + c * 16;
        cp16(d,          hi + row * KP + c * 8);
        cp16(d + TILE_B, lo + row * KP + c * 8);
    }
}

// copy stage buffer (128 rows x 64 words) -> global comb tile, uint4 both sides
__device__ __forceinline__ void copy_out(const char* sm, int buf, uint4* __restrict__ gout4,
                                         size_t rowbase_h, int jt, int tid) {
    const char* stg = sm + SM_STG + buf * STG_BUF;
    #pragma unroll
    for (int it = 0; it < 4; ++it) {
        int idx = tid + it * 512;         // 2048 uint4
        int row = idx >> 4, q = idx & 15;
        uint4 v = *(const uint4*)(stg + row * STG_S + q * 16);
        gout4[(rowbase_h + (size_t)row * RP + jt * 128) / 8 + q] = v;
    }
}

__global__ __launch_bounds__(512, 1) void main_kernel() {
    extern __shared__ char sm[];
    uint32_t smb = smem_u32(sm);
    int tid = threadIdx.x;
    int w = tid >> 5, l = tid & 31;
    int n  = blockIdx.y;
    int i0 = blockIdx.x * 128;
    int wm = w >> 2, wn = w & 3;

    float* rT_s  = (float*)(sm + SM_RT);
    float* rI_s  = (float*)(sm + SM_RI);
    int*   red_s = (int*)  (sm + SM_RED);

    // ---- load A tile (once) + rI + init min ----
    const __nv_bfloat16* Ahi = g_hi + ((size_t)n * RP + i0) * KP;
    const __nv_bfloat16* Alo = g_lo + ((size_t)n * RP + i0) * KP;
    for (int t = tid; t < 1280; t += 512) {
        int row = t / 10, c = t - row * 10;
        *(uint4*)(sm + SM_AH + row * TS + c * 16) = *(const uint4*)(Ahi + row * KP + c * 8);
        *(uint4*)(sm + SM_AL + row * TS + c * 16) = *(const uint4*)(Alo + row * KP + c * 8);
    }
    if (tid < 128) {
        rI_s[tid]  = g_r[n * RP + i0 + tid];
        red_s[tid] = 0x7F7FFFFF;   // FLT_MAX
    }
    __syncthreads();

    // ---- per-lane geometry ----
    int qr = l >> 2;
    int qc = (l & 3) * 2;
    int lrow = (l & 7) + ((l >> 3) & 1) * 8;
    int lcol = (l >> 4) * 16;
    int aoff = (wm * 32 + lrow) * TS + lcol;
    int boff = (wn * 32 + lrow) * TS + lcol;

    float ri[2][2];
    #pragma unroll
    for (int mt = 0; mt < 2; ++mt)
        #pragma unroll
        for (int h = 0; h < 2; ++h)
            ri[mt][h] = rI_s[wm * 32 + mt * 16 + qr + h * 8];

    const __nv_bfloat16* Bhi0 = g_hi + (size_t)(NB + n) * RP * KP;
    const __nv_bfloat16* Blo0 = g_lo + (size_t)(NB + n) * RP * KP;
    const float* rTg = g_r + (NB + n) * RP;

    float rmin[2][2] = {{1e30f, 1e30f}, {1e30f, 1e30f}};
    uint4* gout4 = (uint4*)g_comb;
    size_t rowbase = ((size_t)n * RP + i0) * RP;   // in halfs

    // preload j=0
    load_B_async(smb + SM_B0, Bhi0, Blo0, tid);
    CP_COMMIT();
    if (tid < 128) rT_s[tid] = rTg[tid];

    for (int j = 0; j < NJ; ++j) {
        int cur = j & 1;
        CP_WAIT0();
        __syncthreads();               // B[cur] ready; stage[cur] writes of j-2 all read

        if (j + 1 < NJ) {
            load_B_async(smb + SM_B0 + (cur ^ 1) * BUF_B,
                         Bhi0 + (size_t)(j + 1) * 128 * KP,
                         Blo0 + (size_t)(j + 1) * 128 * KP, tid);
            CP_COMMIT();
            if (tid < 128) rT_s[(cur ^ 1) * 128 + tid] = rTg[(j + 1) * 128 + tid];
        }

        // deferred copy-out of tile j-1 (stage[cur^1], fully written before top sync)
        if (j > 0) copy_out(sm, cur ^ 1, gout4, rowbase, j - 1, tid);

        // ---- GEMM: 3-way split bf16 with A-hi/B-hi fragment reuse ----
        float acc[2][4][4];
        #pragma unroll
        for (int mt = 0; mt < 2; ++mt)
            #pragma unroll
            for (int nt = 0; nt < 4; ++nt)
                #pragma unroll
                for (int q = 0; q < 4; ++q) acc[mt][nt][q] = 0.0f;

        uint32_t Bcur = smb + SM_B0 + cur * BUF_B;
        #pragma unroll
        for (int kk = 0; kk < 5; ++kk) {
            uint32_t AH0[4], AH1[4], AL0[4], AL1[4], BH0[4], BH1[4], BL0[4], BL1[4];
            ldsm4(BH0, Bcur + boff + kk * 32);
            ldsm4(BH1, Bcur + boff + 16 * TS + kk * 32);
            ldsm4(AH0, smb + SM_AH + aoff + kk * 32);
            ldsm4(AH1, smb + SM_AH + aoff + 16 * TS + kk * 32);
            // hh
            mma16816(acc[0][0], AH0, BH0[0], BH0[2]);
            mma16816(acc[0][1], AH0, BH0[1], BH0[3]);
            mma16816(acc[0][2], AH0, BH1[0], BH1[2]);
            mma16816(acc[0][3], AH0, BH1[1], BH1[3]);
            mma16816(acc[1][0], AH1, BH0[0], BH0[2]);
            mma16816(acc[1][1], AH1, BH0[1], BH0[3]);
            mma16816(acc[1][2], AH1, BH1[0], BH1[2]);
            mma16816(acc[1][3], AH1, BH1[1], BH1[3]);
            // lh (reuse BH)
            ldsm4(AL0, smb + SM_AL + aoff + kk * 32);
            ldsm4(AL1, smb + SM_AL + aoff + 16 * TS + kk * 32);
            mma16816(acc[0][0], AL0, BH0[0], BH0[2]);
            mma16816(acc[0][1], AL0, BH0[1], BH0[3]);
            mma16816(acc[0][2], AL0, BH1[0], BH1[2]);
            mma16816(acc[0][3], AL0, BH1[1], BH1[3]);
            mma16816(acc[1][0], AL1, BH0[0], BH0[2]);
            mma16816(acc[1][1], AL1, BH0[1], BH0[3]);
            mma16816(acc[1][2], AL1, BH1[0], BH1[2]);
            mma16816(acc[1][3], AL1, BH1[1], BH1[3]);
            // hl (reuse AH)
            ldsm4(BL0, Bcur + TILE_B + boff + kk * 32);
            ldsm4(BL1, Bcur + TILE_B + boff + 16 * TS + kk * 32);
            mma16816(acc[0][0], AH0, BL0[0], BL0[2]);
            mma16816(acc[0][1], AH0, BL0[1], BL0[3]);
            mma16816(acc[0][2], AH0, BL1[0], BL1[2]);
            mma16816(acc[0][3], AH0, BL1[1], BL1[3]);
            mma16816(acc[1][0], AH1, BL0[0], BL0[2]);
            mma16816(acc[1][1], AH1, BL0[1], BL0[3]);
            mma16816(acc[1][2], AH1, BL1[0], BL1[2]);
            mma16816(acc[1][3], AH1, BL1[1], BL1[3]);
        }

        // ---- epilogue: comb, row-min, stage fp16 into stage[cur] ----
        char* stg = sm + SM_STG + cur * STG_BUF;
        float rt[4][2];
        #pragma unroll
        for (int nt = 0; nt < 4; ++nt) {
            rt[nt][0] = rT_s[cur * 128 + wn * 32 + nt * 8 + qc];
            rt[nt][1] = rT_s[cur * 128 + wn * 32 + nt * 8 + qc + 1];
        }
        #pragma unroll
        for (int mt = 0; mt < 2; ++mt)
            #pragma unroll
            for (int nt = 0; nt < 4; ++nt)
                #pragma unroll
                for (int h = 0; h < 2; ++h) {
                    float c0 = fmaxf(fmaf(-2.0f, acc[mt][nt][2*h],   ri[mt][h] + rt[nt][0]), 0.0f);
                    float c1 = fmaxf(fmaf(-2.0f, acc[mt][nt][2*h+1], ri[mt][h] + rt[nt][1]), 0.0f);
                    rmin[mt][h] = fminf(rmin[mt][h], fminf(c0, c1));
                    int srow = wm * 32 + mt * 16 + h * 8 + qr;
                    int scol = wn * 32 + nt * 8 + qc;
                    *(uint32_t*)(stg + srow * STG_S + scol * 2) = pack_f16x2(c0, c1);
                }
    }
    __syncthreads();
    copy_out(sm, (NJ - 1) & 1, gout4, rowbase, NJ - 1, tid);

    // ---- row minima -> per-row exp coefficients ----
    #pragma unroll
    for (int mt = 0; mt < 2; ++mt)
        #pragma unroll
        for (int h = 0; h < 2; ++h) {
            float v = rmin[mt][h];
            v = fminf(v, __shfl_xor_sync(0xffffffffu, v, 1));
            v = fminf(v, __shfl_xor_sync(0xffffffffu, v, 2));
            if ((l & 3) == 0)
                atomicMin(&red_s[wm * 32 + mt * 16 + qr + h * 8], __float_as_int(v));
        }
    __syncthreads();
    if (tid < 128) {
        float dmin = __int_as_float(red_s[tid]);
        float m = -L2E / (0.5f * (dmin + 1e-5f));
        g_m[n * RP + i0 + tid] = m;
        g_b[n * RP + i0 + tid] = -dmin * m;
    }
}

// ---------------- per-row exp-sum kernel (memory-bound) ----------------
__global__ __launch_bounds__(128) void row_kernel() {
    int n = blockIdx.y;
    int r = n * RP + blockIdx.x;          // blockIdx.x < P
    float m = g_m[r], b = g_b[r];
    const uint4* p = (const uint4*)(g_comb + (size_t)r * RP);

    float s = 0.0f;
    #pragma unroll
    for (int it = 0; it < 4; ++it) {
        uint4 v = p[threadIdx.x + it * 128];
        #pragma unroll
        for (int q = 0; q < 4; ++q) {
            unsigned u = (&v.x)[q];
            float2 f = __half22float2(*(__half2*)&u);
            s += ex2f(fmaf(f.x, m, b));
            s += ex2f(fmaf(f.y, m, b));
        }
    }
    // block reduce
    #pragma unroll
    for (int off = 16; off >= 1; off >>= 1)
        s += __shfl_xor_sync(0xffffffffu, s, off);
    __shared__ float red[4];
    if ((threadIdx.x & 31) == 0) red[threadIdx.x >> 5] = s;
    __syncthreads();
    if (threadIdx.x == 0) {
        float t = red[0] + red[1] + red[2] + red[3];
        atomicAdd(&g_acc[n], 1.0f / t);
    }
}

// ---------------- final scalar ----------------
__global__ void final_kernel(float* out) {
    float L = 0.0f;
    #pragma unroll
    for (int n = 0; n < NB; ++n)
        L += -logf(g_acc[n] * (1.0f / (float)P));
    out[0] = L;
}

// ---------------- launch ----------------
extern "C" void kernel_launch(void* const* d_in, const int* in_sizes, int n_in,
                              void* d_out, int out_size) {
    const float* outp = (const float*)d_in[0];
    const float* targ = (const float*)d_in[1];
    float* out = (float*)d_out;

    cudaFuncSetAttribute(main_kernel, cudaFuncAttributeMaxDynamicSharedMemorySize, SMEM_BYTES);

    init_kernel<<<1, 32>>>();
    const int TOT = 2 * NB * RP * KP;
    feat_kernel<<<(TOT + 255) / 256, 256>>>(outp, targ);
    rsq_kernel<<<(2 * NB * RP + 255) / 256, 256>>>();
    main_kernel<<<dim3(NI, NB), 512, SMEM_BYTES>>>();
    row_kernel<<<dim3(P, NB), 128>>>();
    final_kernel<<<1, 1>>>(out);
}

// round 8
// speedup vs baseline: 2.8993x; 1.0240x over previous
#include <cuda_runtime.h>
#include <cuda_bf16.h>
#include <cuda_fp16.h>
#include <math.h>
#include <stdint.h>

// ---------------- problem constants ----------------
#define NB 4
#define HF 63
#define P  3969
#define RP 4096            // rows padded per image
#define KP 80              // 75 feats + 2 coord feats + 3 zero pad
#define NI 32
#define NJ 32
#define IN_H 67
#define CS  0.31622776601683794f   // sqrt(0.1)
#define L2E 1.4426950408889634f

// ---------------- scratch ----------------
__device__ __nv_bfloat16 g_hi[(size_t)2 * NB * RP * KP];
__device__ __nv_bfloat16 g_lo[(size_t)2 * NB * RP * KP];
__device__ float g_r[2 * NB * RP];
__device__ float g_m[NB * RP];
__device__ float g_b[NB * RP];
__device__ __half g_comb[(size_t)NB * RP * RP];   // 134 MB, stores s = rT - 2*dot
__device__ float g_acc[NB];

// ---------------- helpers ----------------
__device__ __forceinline__ uint32_t smem_u32(const void* p) {
    uint32_t a;
    asm("{ .reg .u64 t; cvta.to.shared.u64 t, %1; cvt.u32.u64 %0, t; }" : "=r"(a) : "l"(p));
    return a;
}
__device__ __forceinline__ void cp16(uint32_t dst, const void* src) {
    asm volatile("cp.async.cg.shared.global [%0], [%1], 16;" :: "r"(dst), "l"(src));
}
#define CP_COMMIT() asm volatile("cp.async.commit_group;" ::: "memory")
#define CP_WAIT0()  asm volatile("cp.async.wait_group 0;" ::: "memory")

__device__ __forceinline__ void ldsm4(uint32_t* r, uint32_t addr) {
    asm volatile("ldmatrix.sync.aligned.m8n8.x4.shared.b16 {%0,%1,%2,%3}, [%4];"
        : "=r"(r[0]), "=r"(r[1]), "=r"(r[2]), "=r"(r[3]) : "r"(addr));
}
__device__ __forceinline__ void mma16816(float* d, const uint32_t* a, uint32_t b0, uint32_t b1) {
    asm volatile("mma.sync.aligned.m16n8k16.row.col.f32.bf16.bf16.f32 "
        "{%0,%1,%2,%3},{%4,%5,%6,%7},{%8,%9},{%0,%1,%2,%3};"
        : "+f"(d[0]), "+f"(d[1]), "+f"(d[2]), "+f"(d[3])
        : "r"(a[0]), "r"(a[1]), "r"(a[2]), "r"(a[3]), "r"(b0), "r"(b1));
}
__device__ __forceinline__ float ex2f(float x) {
    float y; asm("ex2.approx.f32 %0, %1;" : "=f"(y) : "f"(x)); return y;
}
__device__ __forceinline__ uint32_t pack_f16x2(float lo, float hi) {
    uint32_t u;
    asm("cvt.rn.f16x2.f32 %0, %1, %2;" : "=r"(u) : "f"(hi), "f"(lo));
    return u;
}
// monotone float<->uint for atomicMin over possibly-negative floats
__device__ __forceinline__ unsigned fenc(float f) {
    int b = __float_as_int(f);
    return (unsigned)(b >= 0 ? (b | 0x80000000) : ~b);
}
__device__ __forceinline__ float fdec(unsigned u) {
    int b = (u & 0x80000000u) ? (int)(u ^ 0x80000000u) : ~(int)u;
    return __int_as_float(b);
}

// ---------------- prep kernels ----------------
__global__ void init_kernel() { if (threadIdx.x < NB) g_acc[threadIdx.x] = 0.0f; }

__global__ void feat_kernel(const float* __restrict__ outp, const float* __restrict__ targ) {
    int idx = blockIdx.x * blockDim.x + threadIdx.x;
    const int TOT = 2 * NB * RP * KP;
    if (idx >= TOT) return;
    int k     = idx % KP;
    int row   = (idx / KP) % RP;
    int n     = (idx / (KP * RP)) % NB;
    int which = idx / (KP * RP * NB);
    float v = 0.0f;
    if (row < P) {
        int y = row / HF, x = row - y * HF;
        if (k < 75) {
            int c = k / 25, t = k - c * 25, dy = t / 5, dx = t - dy * 5;
            const float* src = which ? targ : outp;
            v = src[((n * 3 + c) * IN_H + y + dy) * IN_H + x + dx] - 0.5f;
        } else if (k == 75) v = CS * (float)y * (1.0f / 62.0f);
        else if (k == 76)   v = CS * (float)x * (1.0f / 62.0f);
    }
    __nv_bfloat16 h = __float2bfloat16(v);
    float lo = v - __bfloat162float(h);
    g_hi[idx] = h;
    g_lo[idx] = __float2bfloat16(lo);
}

__global__ void rsq_kernel() {
    int idx = blockIdx.x * blockDim.x + threadIdx.x;
    if (idx >= 2 * NB * RP) return;
    int row   = idx % RP;
    int which = idx / (NB * RP);
    size_t base = (size_t)idx * KP;
    float s = 0.0f;
    #pragma unroll 16
    for (int k = 0; k < KP; ++k) {
        float v = __bfloat162float(g_hi[base + k]) + __bfloat162float(g_lo[base + k]);
        s = fmaf(v, v, s);
    }
    if (which == 1 && row >= P) s = 1e9f;   // T pad rows: s huge -> fp16 inf -> exp 0
    g_r[idx] = s;
}

// ---------------- main GEMM kernel ----------------
#define TS     176                 // smem row stride (bytes), ldmatrix conflict-free
#define TILE_B (128 * TS)          // 22528
#define SM_RT  0                   // 2 x 128 f
#define SM_RI  1024
#define SM_RED 1536                // encoded uint row-min
#define SM_AH  4096
#define SM_AL  (SM_AH + TILE_B)
#define SM_B0  (SM_AL + TILE_B)    // 49152
#define BUF_B  (2 * TILE_B)        // hi+lo per stage
#define SM_STG (SM_B0 + 2 * BUF_B) // 139264
#define STG_S  272                 // stage row stride bytes (68 words -> conflict-free)
#define STG_BUF (128 * STG_S)      // 34816 per stage buffer
#define SMEM_BYTES (SM_STG + 2 * STG_BUF)   // 208896

__device__ __forceinline__ void load_B_async(uint32_t smB,
                                             const __nv_bfloat16* __restrict__ hi,
                                             const __nv_bfloat16* __restrict__ lo, int tid) {
    for (int t = tid; t < 1280; t += 512) {
        int row = t / 10, c = t - row * 10;
        uint32_t d = smB + row * TS + c * 16;
        cp16(d,          hi + row * KP + c * 8);
        cp16(d + TILE_B, lo + row * KP + c * 8);
    }
}

// copy stage buffer (128 rows x 64 words) -> global comb tile, uint4 both sides
__device__ __forceinline__ void copy_out(const char* sm, int buf, uint4* __restrict__ dst0,
                                         int jt, int tid) {
    const char* stg = sm + SM_STG + buf * STG_BUF;
    uint4* dst = dst0 + jt * 16;
    #pragma unroll
    for (int it = 0; it < 4; ++it) {
        int idx = tid + it * 512;         // 2048 uint4
        int row = idx >> 4, q = idx & 15;
        uint4 v = *(const uint4*)(stg + row * STG_S + q * 16);
        dst[row * (RP / 8) + q] = v;
    }
}

__global__ __launch_bounds__(512, 1) void main_kernel() {
    extern __shared__ char sm[];
    uint32_t smb = smem_u32(sm);
    int tid = threadIdx.x;
    int w = tid >> 5, l = tid & 31;
    int n  = blockIdx.y;
    int i0 = blockIdx.x * 128;
    int wm = w >> 2, wn = w & 3;

    float*    rT_s  = (float*)(sm + SM_RT);
    float*    rI_s  = (float*)(sm + SM_RI);
    unsigned* red_s = (unsigned*)(sm + SM_RED);

    // ---- load A tile (once) + rI + init min ----
    const __nv_bfloat16* Ahi = g_hi + ((size_t)n * RP + i0) * KP;
    const __nv_bfloat16* Alo = g_lo + ((size_t)n * RP + i0) * KP;
    for (int t = tid; t < 1280; t += 512) {
        int row = t / 10, c = t - row * 10;
        *(uint4*)(sm + SM_AH + row * TS + c * 16) = *(const uint4*)(Ahi + row * KP + c * 8);
        *(uint4*)(sm + SM_AL + row * TS + c * 16) = *(const uint4*)(Alo + row * KP + c * 8);
    }
    if (tid < 128) {
        rI_s[tid]  = g_r[n * RP + i0 + tid];
        red_s[tid] = 0xFFFFFFFFu;
    }
    __syncthreads();

    // ---- per-lane geometry ----
    int qr = l >> 2;
    int qc = (l & 3) * 2;
    int lrow = (l & 7) + ((l >> 3) & 1) * 8;
    int lcol = (l >> 4) * 16;
    int aoff = (wm * 32 + lrow) * TS + lcol;
    int boff = (wn * 32 + lrow) * TS + lcol;

    const __nv_bfloat16* Bhi0 = g_hi + (size_t)(NB + n) * RP * KP;
    const __nv_bfloat16* Blo0 = g_lo + (size_t)(NB + n) * RP * KP;
    const float* rTg = g_r + (NB + n) * RP;

    __half2 hmin[2][2];
    #pragma unroll
    for (int mt = 0; mt < 2; ++mt)
        #pragma unroll
        for (int h = 0; h < 2; ++h)
            hmin[mt][h] = __floats2half2_rn(65504.0f, 65504.0f);

    uint4* gout4 = (uint4*)(g_comb + ((size_t)n * RP + i0) * RP);

    // preload j=0
    load_B_async(smb + SM_B0, Bhi0, Blo0, tid);
    CP_COMMIT();
    if (tid < 128) rT_s[tid] = rTg[tid];

    for (int j = 0; j < NJ; ++j) {
        int cur = j & 1;
        CP_WAIT0();
        __syncthreads();               // B[cur] ready; stage[cur] writes of j-2 all read

        if (j + 1 < NJ) {
            load_B_async(smb + SM_B0 + (cur ^ 1) * BUF_B,
                         Bhi0 + (size_t)(j + 1) * 128 * KP,
                         Blo0 + (size_t)(j + 1) * 128 * KP, tid);
            CP_COMMIT();
            if (tid < 128) rT_s[(cur ^ 1) * 128 + tid] = rTg[(j + 1) * 128 + tid];
        }

        // deferred copy-out of tile j-1 (stage[cur^1], fully written before top sync)
        if (j > 0) copy_out(sm, cur ^ 1, gout4, j - 1, tid);

        // ---- GEMM: 3-way split bf16 with A-hi/B-hi fragment reuse ----
        float acc[2][4][4];
        #pragma unroll
        for (int mt = 0; mt < 2; ++mt)
            #pragma unroll
            for (int nt = 0; nt < 4; ++nt)
                #pragma unroll
                for (int q = 0; q < 4; ++q) acc[mt][nt][q] = 0.0f;

        uint32_t Bcur = smb + SM_B0 + cur * BUF_B;
        #pragma unroll
        for (int kk = 0; kk < 5; ++kk) {
            uint32_t AH0[4], AH1[4], AL0[4], AL1[4], BH0[4], BH1[4], BL0[4], BL1[4];
            ldsm4(BH0, Bcur + boff + kk * 32);
            ldsm4(BH1, Bcur + boff + 16 * TS + kk * 32);
            ldsm4(AH0, smb + SM_AH + aoff + kk * 32);
            ldsm4(AH1, smb + SM_AH + aoff + 16 * TS + kk * 32);
            // hh
            mma16816(acc[0][0], AH0, BH0[0], BH0[2]);
            mma16816(acc[0][1], AH0, BH0[1], BH0[3]);
            mma16816(acc[0][2], AH0, BH1[0], BH1[2]);
            mma16816(acc[0][3], AH0, BH1[1], BH1[3]);
            mma16816(acc[1][0], AH1, BH0[0], BH0[2]);
            mma16816(acc[1][1], AH1, BH0[1], BH0[3]);
            mma16816(acc[1][2], AH1, BH1[0], BH1[2]);
            mma16816(acc[1][3], AH1, BH1[1], BH1[3]);
            // lh (reuse BH)
            ldsm4(AL0, smb + SM_AL + aoff + kk * 32);
            ldsm4(AL1, smb + SM_AL + aoff + 16 * TS + kk * 32);
            mma16816(acc[0][0], AL0, BH0[0], BH0[2]);
            mma16816(acc[0][1], AL0, BH0[1], BH0[3]);
            mma16816(acc[0][2], AL0, BH1[0], BH1[2]);
            mma16816(acc[0][3], AL0, BH1[1], BH1[3]);
            mma16816(acc[1][0], AL1, BH0[0], BH0[2]);
            mma16816(acc[1][1], AL1, BH0[1], BH0[3]);
            mma16816(acc[1][2], AL1, BH1[0], BH1[2]);
            mma16816(acc[1][3], AL1, BH1[1], BH1[3]);
            // hl (reuse AH)
            ldsm4(BL0, Bcur + TILE_B + boff + kk * 32);
            ldsm4(BL1, Bcur + TILE_B + boff + 16 * TS + kk * 32);
            mma16816(acc[0][0], AH0, BL0[0], BL0[2]);
            mma16816(acc[0][1], AH0, BL0[1], BL0[3]);
            mma16816(acc[0][2], AH0, BL1[0], BL1[2]);
            mma16816(acc[0][3], AH0, BL1[1], BL1[3]);
            mma16816(acc[1][0], AH1, BL0[0], BL0[2]);
            mma16816(acc[1][1], AH1, BL0[1], BL0[3]);
            mma16816(acc[1][2], AH1, BL1[0], BL1[2]);
            mma16816(acc[1][3], AH1, BL1[1], BL1[3]);
        }

        // ---- epilogue: s = rT - 2*dot, fp16 pack, hmin2 row-min, stage ----
        char* stg = sm + SM_STG + cur * STG_BUF;
        #pragma unroll
        for (int nt = 0; nt < 4; ++nt) {
            float2 rtp = *(const float2*)&rT_s[cur * 128 + wn * 32 + nt * 8 + qc];
            #pragma unroll
            for (int mt = 0; mt < 2; ++mt)
                #pragma unroll
                for (int h = 0; h < 2; ++h) {
                    float s0 = fmaf(-2.0f, acc[mt][nt][2 * h],     rtp.x);
                    float s1 = fmaf(-2.0f, acc[mt][nt][2 * h + 1], rtp.y);
                    uint32_t u = pack_f16x2(s0, s1);
                    hmin[mt][h] = __hmin2(hmin[mt][h], *(__half2*)&u);
                    int srow = wm * 32 + mt * 16 + h * 8 + qr;
                    int scol = wn * 32 + nt * 8 + qc;
                    *(uint32_t*)(stg + srow * STG_S + scol * 2) = u;
                }
        }
    }
    __syncthreads();
    copy_out(sm, (NJ - 1) & 1, gout4, NJ - 1, tid);

    // ---- row minima -> per-row exp coefficients ----
    #pragma unroll
    for (int mt = 0; mt < 2; ++mt)
        #pragma unroll
        for (int h = 0; h < 2; ++h) {
            uint32_t u = *(uint32_t*)&hmin[mt][h];
            #pragma unroll
            for (int off = 1; off <= 2; off <<= 1) {
                uint32_t v = __shfl_xor_sync(0xffffffffu, u, off);
                __half2 r = __hmin2(*(__half2*)&u, *(__half2*)&v);
                u = *(uint32_t*)&r;
            }
            if ((l & 3) == 0) {
                __half2 hv = *(__half2*)&u;
                float smin = fminf(__low2float(hv), __high2float(hv));
                atomicMin(&red_s[wm * 32 + mt * 16 + qr + h * 8], fenc(smin));
            }
        }
    __syncthreads();
    if (tid < 128) {
        float smin = fdec(red_s[tid]);
        float dmin = rI_s[tid] + smin;
        float m = -L2E / (0.5f * (dmin + 1e-5f));
        g_m[n * RP + i0 + tid] = m;
        g_b[n * RP + i0 + tid] = -smin * m;
    }
}

// ---------------- per-row exp-sum kernel (memory-bound) ----------------
__global__ __launch_bounds__(128) void row_kernel() {
    int n = blockIdx.y;
    int r = n * RP + blockIdx.x;          // blockIdx.x < P
    float m = g_m[r], b = g_b[r];
    const uint4* p = (const uint4*)(g_comb + (size_t)r * RP);

    float s = 0.0f;
    #pragma unroll
    for (int it = 0; it < 4; ++it) {
        uint4 v = p[threadIdx.x + it * 128];
        #pragma unroll
        for (int q = 0; q < 4; ++q) {
            unsigned u = (&v.x)[q];
            float2 f = __half22float2(*(__half2*)&u);
            s += ex2f(fmaf(f.x, m, b));
            s += ex2f(fmaf(f.y, m, b));
        }
    }
    // block reduce
    #pragma unroll
    for (int off = 16; off >= 1; off >>= 1)
        s += __shfl_xor_sync(0xffffffffu, s, off);
    __shared__ float red[4];
    if ((threadIdx.x & 31) == 0) red[threadIdx.x >> 5] = s;
    __syncthreads();
    if (threadIdx.x == 0) {
        float t = red[0] + red[1] + red[2] + red[3];
        atomicAdd(&g_acc[n], 1.0f / t);
    }
}

// ---------------- final scalar ----------------
__global__ void final_kernel(float* out) {
    float L = 0.0f;
    #pragma unroll
    for (int n = 0; n < NB; ++n)
        L += -logf(g_acc[n] * (1.0f / (float)P));
    out[0] = L;
}

// ---------------- launch ----------------
extern "C" void kernel_launch(void* const* d_in, const int* in_sizes, int n_in,
                              void* d_out, int out_size) {
    const float* outp = (const float*)d_in[0];
    const float* targ = (const float*)d_in[1];
    float* out = (float*)d_out;

    cudaFuncSetAttribute(main_kernel, cudaFuncAttributeMaxDynamicSharedMemorySize, SMEM_BYTES);

    init_kernel<<<1, 32>>>();
    const int TOT = 2 * NB * RP * KP;
    feat_kernel<<<(TOT + 255) / 256, 256>>>(outp, targ);
    rsq_kernel<<<(2 * NB * RP + 255) / 256, 256>>>();
    main_kernel<<<dim3(NI, NB), 512, SMEM_BYTES>>>();
    row_kernel<<<dim3(P, NB), 128>>>();
    final_kernel<<<1, 1>>>(out);
}

// round 9
// speedup vs baseline: 3.2778x; 1.1305x over previous
#include <cuda_runtime.h>
#include <cuda_bf16.h>
#include <cuda_fp16.h>
#include <math.h>
#include <stdint.h>

// ---------------- problem constants ----------------
#define NB 4
#define HF 63
#define P  3969
#define RP 4096            // rows padded per image
#define KP 80              // 75 feats + 2 coord feats + 3 zero pad
#define NI 32
#define NJ 32
#define IN_H 67
#define CS  0.31622776601683794f   // sqrt(0.1)
#define L2E 1.4426950408889634f

// ---------------- scratch ----------------
__device__ __nv_bfloat16 g_hi[(size_t)2 * NB * RP * KP];
__device__ __nv_bfloat16 g_lo[(size_t)2 * NB * RP * KP];
__device__ float g_r[2 * NB * RP];
__device__ float g_m[NB * RP];
__device__ float g_b[NB * RP];
__device__ __half g_comb[(size_t)NB * RP * RP];   // 134 MB, stores s = rT - 2*dot
__device__ float g_acc[NB];

// ---------------- helpers ----------------
__device__ __forceinline__ uint32_t smem_u32(const void* p) {
    uint32_t a;
    asm("{ .reg .u64 t; cvta.to.shared.u64 t, %1; cvt.u32.u64 %0, t; }" : "=r"(a) : "l"(p));
    return a;
}
__device__ __forceinline__ void cp16(uint32_t dst, const void* src) {
    asm volatile("cp.async.cg.shared.global [%0], [%1], 16;" :: "r"(dst), "l"(src));
}
#define CP_COMMIT() asm volatile("cp.async.commit_group;" ::: "memory")
#define CP_WAIT0()  asm volatile("cp.async.wait_group 0;" ::: "memory")

__device__ __forceinline__ void ldsm4(uint32_t* r, uint32_t addr) {
    asm volatile("ldmatrix.sync.aligned.m8n8.x4.shared.b16 {%0,%1,%2,%3}, [%4];"
        : "=r"(r[0]), "=r"(r[1]), "=r"(r[2]), "=r"(r[3]) : "r"(addr));
}
__device__ __forceinline__ void mma16816(float* d, const uint32_t* a, uint32_t b0, uint32_t b1) {
    asm volatile("mma.sync.aligned.m16n8k16.row.col.f32.bf16.bf16.f32 "
        "{%0,%1,%2,%3},{%4,%5,%6,%7},{%8,%9},{%0,%1,%2,%3};"
        : "+f"(d[0]), "+f"(d[1]), "+f"(d[2]), "+f"(d[3])
        : "r"(a[0]), "r"(a[1]), "r"(a[2]), "r"(a[3]), "r"(b0), "r"(b1));
}
__device__ __forceinline__ float ex2f(float x) {
    float y; asm("ex2.approx.f32 %0, %1;" : "=f"(y) : "f"(x)); return y;
}
__device__ __forceinline__ uint32_t pack_f16x2(float lo, float hi) {
    uint32_t u;
    asm("cvt.rn.f16x2.f32 %0, %1, %2;" : "=r"(u) : "f"(hi), "f"(lo));
    return u;
}
// monotone float<->uint for atomicMin over possibly-negative floats
__device__ __forceinline__ unsigned fenc(float f) {
    int b = __float_as_int(f);
    return (unsigned)(b >= 0 ? (b | 0x80000000) : ~b);
}
__device__ __forceinline__ float fdec(unsigned u) {
    int b = (u & 0x80000000u) ? (int)(u ^ 0x80000000u) : ~(int)u;
    return __int_as_float(b);
}

// ---------------- prep kernels ----------------
__global__ void init_kernel() { if (threadIdx.x < NB) g_acc[threadIdx.x] = 0.0f; }

__global__ void feat_kernel(const float* __restrict__ outp, const float* __restrict__ targ) {
    int idx = blockIdx.x * blockDim.x + threadIdx.x;
    const int TOT = 2 * NB * RP * KP;
    if (idx >= TOT) return;
    int k     = idx % KP;
    int row   = (idx / KP) % RP;
    int n     = (idx / (KP * RP)) % NB;
    int which = idx / (KP * RP * NB);
    float v = 0.0f;
    if (row < P) {
        int y = row / HF, x = row - y * HF;
        if (k < 75) {
            int c = k / 25, t = k - c * 25, dy = t / 5, dx = t - dy * 5;
            const float* src = which ? targ : outp;
            v = src[((n * 3 + c) * IN_H + y + dy) * IN_H + x + dx] - 0.5f;
        } else if (k == 75) v = CS * (float)y * (1.0f / 62.0f);
        else if (k == 76)   v = CS * (float)x * (1.0f / 62.0f);
    }
    __nv_bfloat16 h = __float2bfloat16(v);
    float lo = v - __bfloat162float(h);
    g_hi[idx] = h;
    g_lo[idx] = __float2bfloat16(lo);
}

__global__ void rsq_kernel() {
    int idx = blockIdx.x * blockDim.x + threadIdx.x;
    if (idx >= 2 * NB * RP) return;
    int row   = idx % RP;
    int which = idx / (NB * RP);
    size_t base = (size_t)idx * KP;
    float s = 0.0f;
    #pragma unroll 16
    for (int k = 0; k < KP; ++k) {
        float v = __bfloat162float(g_hi[base + k]) + __bfloat162float(g_lo[base + k]);
        s = fmaf(v, v, s);
    }
    if (which == 1 && row >= P) s = 1e9f;   // T pad rows: s huge -> fp16 inf -> exp 0
    g_r[idx] = s;
}

// ---------------- main GEMM kernel ----------------
#define TS     176                 // smem row stride (bytes), ldmatrix conflict-free
#define TILE_B (128 * TS)          // 22528
#define SM_RT  0                   // 2 x 128 f
#define SM_RI  1024
#define SM_RED 1536                // encoded uint row-min
#define SM_AH  2048
#define SM_B0  (SM_AH + TILE_B)    // 24576; 2 stages x (hi + lo)
#define BUF_B  (2 * TILE_B)        // hi+lo per stage = 45056
#define SMEM_BYTES (SM_B0 + 2 * BUF_B)   // 114688 (112 KB)

__device__ __forceinline__ void load_B_async(uint32_t smB,
                                             const __nv_bfloat16* __restrict__ hi,
                                             const __nv_bfloat16* __restrict__ lo, int tid) {
    for (int t = tid; t < 1280; t += 512) {
        int row = t / 10, c = t - row * 10;
        uint32_t d = smB + row * TS + c * 16;
        cp16(d,          hi + row * KP + c * 8);
        cp16(d + TILE_B, lo + row * KP + c * 8);
    }
}

__global__ __launch_bounds__(512, 1) void main_kernel() {
    extern __shared__ char sm[];
    uint32_t smb = smem_u32(sm);
    int tid = threadIdx.x;
    int w = tid >> 5, l = tid & 31;
    int n  = blockIdx.y;
    int i0 = blockIdx.x * 128;
    int wm = w >> 2, wn = w & 3;

    float*    rT_s  = (float*)(sm + SM_RT);
    float*    rI_s  = (float*)(sm + SM_RI);
    unsigned* red_s = (unsigned*)(sm + SM_RED);

    // ---- load A_hi tile (once) + rI + init min ----
    const __nv_bfloat16* Ahi = g_hi + ((size_t)n * RP + i0) * KP;
    for (int t = tid; t < 1280; t += 512) {
        int row = t / 10, c = t - row * 10;
        *(uint4*)(sm + SM_AH + row * TS + c * 16) = *(const uint4*)(Ahi + row * KP + c * 8);
    }
    if (tid < 128) {
        rI_s[tid]  = g_r[n * RP + i0 + tid];
        red_s[tid] = 0xFFFFFFFFu;
    }
    __syncthreads();

    // ---- per-lane geometry ----
    int qr = l >> 2;
    int qc = (l & 3) * 2;
    int lrow = (l & 7) + ((l >> 3) & 1) * 8;
    int lcol = (l >> 4) * 16;
    int aoff = (wm * 32 + lrow) * TS + lcol;
    int boff = (wn * 32 + lrow) * TS + lcol;

    const __nv_bfloat16* Bhi0 = g_hi + (size_t)(NB + n) * RP * KP;
    const __nv_bfloat16* Blo0 = g_lo + (size_t)(NB + n) * RP * KP;
    const float* rTg = g_r + (NB + n) * RP;

    __half2 hmin[2][2];
    #pragma unroll
    for (int mt = 0; mt < 2; ++mt)
        #pragma unroll
        for (int h = 0; h < 2; ++h)
            hmin[mt][h] = __floats2half2_rn(65504.0f, 65504.0f);

    // base pointer for this CTA's comb rows (u32 granularity; qc even)
    uint32_t* gout = (uint32_t*)(g_comb + ((size_t)n * RP + i0) * RP);

    // preload j=0
    load_B_async(smb + SM_B0, Bhi0, Blo0, tid);
    CP_COMMIT();
    if (tid < 128) rT_s[tid] = rTg[tid];

    for (int j = 0; j < NJ; ++j) {
        int cur = j & 1;
        CP_WAIT0();
        __syncthreads();               // B[cur] ready; everyone done reading B[cur^1]

        if (j + 1 < NJ) {
            load_B_async(smb + SM_B0 + (cur ^ 1) * BUF_B,
                         Bhi0 + (size_t)(j + 1) * 128 * KP,
                         Blo0 + (size_t)(j + 1) * 128 * KP, tid);
            CP_COMMIT();
            if (tid < 128) rT_s[(cur ^ 1) * 128 + tid] = rTg[(j + 1) * 128 + tid];
        }

        // ---- GEMM: 2-way split bf16 (hh + hl), A_hi/B_hi fragment reuse ----
        float acc[2][4][4];
        #pragma unroll
        for (int mt = 0; mt < 2; ++mt)
            #pragma unroll
            for (int nt = 0; nt < 4; ++nt)
                #pragma unroll
                for (int q = 0; q < 4; ++q) acc[mt][nt][q] = 0.0f;

        uint32_t Bcur = smb + SM_B0 + cur * BUF_B;
        #pragma unroll
        for (int kk = 0; kk < 5; ++kk) {
            uint32_t AH0[4], AH1[4], BH0[4], BH1[4], BL0[4], BL1[4];
            ldsm4(BH0, Bcur + boff + kk * 32);
            ldsm4(BH1, Bcur + boff + 16 * TS + kk * 32);
            ldsm4(AH0, smb + SM_AH + aoff + kk * 32);
            ldsm4(AH1, smb + SM_AH + aoff + 16 * TS + kk * 32);
            // hh
            mma16816(acc[0][0], AH0, BH0[0], BH0[2]);
            mma16816(acc[0][1], AH0, BH0[1], BH0[3]);
            mma16816(acc[0][2], AH0, BH1[0], BH1[2]);
            mma16816(acc[0][3], AH0, BH1[1], BH1[3]);
            mma16816(acc[1][0], AH1, BH0[0], BH0[2]);
            mma16816(acc[1][1], AH1, BH0[1], BH0[3]);
            mma16816(acc[1][2], AH1, BH1[0], BH1[2]);
            mma16816(acc[1][3], AH1, BH1[1], BH1[3]);
            // hl (reuse AH)
            ldsm4(BL0, Bcur + TILE_B + boff + kk * 32);
            ldsm4(BL1, Bcur + TILE_B + boff + 16 * TS + kk * 32);
            mma16816(acc[0][0], AH0, BL0[0], BL0[2]);
            mma16816(acc[0][1], AH0, BL0[1], BL0[3]);
            mma16816(acc[0][2], AH0, BL1[0], BL1[2]);
            mma16816(acc[0][3], AH0, BL1[1], BL1[3]);
            mma16816(acc[1][0], AH1, BL0[0], BL0[2]);
            mma16816(acc[1][1], AH1, BL0[1], BL0[3]);
            mma16816(acc[1][2], AH1, BL1[0], BL1[2]);
            mma16816(acc[1][3], AH1, BL1[1], BL1[3]);
        }

        // ---- epilogue: s = rT - 2*dot, fp16 pack, hmin2 row-min, direct STG ----
        #pragma unroll
        for (int nt = 0; nt < 4; ++nt) {
            float2 rtp = *(const float2*)&rT_s[cur * 128 + wn * 32 + nt * 8 + qc];
            #pragma unroll
            for (int mt = 0; mt < 2; ++mt)
                #pragma unroll
                for (int h = 0; h < 2; ++h) {
                    float s0 = fmaf(-2.0f, acc[mt][nt][2 * h],     rtp.x);
                    float s1 = fmaf(-2.0f, acc[mt][nt][2 * h + 1], rtp.y);
                    uint32_t u = pack_f16x2(s0, s1);
                    hmin[mt][h] = __hmin2(hmin[mt][h], *(__half2*)&u);
                    int srow = wm * 32 + mt * 16 + h * 8 + qr;
                    int scol = wn * 32 + nt * 8 + qc;
                    gout[((size_t)srow * RP + j * 128 + scol) >> 1] = u;
                }
        }
    }

    // ---- row minima -> per-row exp coefficients ----
    #pragma unroll
    for (int mt = 0; mt < 2; ++mt)
        #pragma unroll
        for (int h = 0; h < 2; ++h) {
            uint32_t u = *(uint32_t*)&hmin[mt][h];
            #pragma unroll
            for (int off = 1; off <= 2; off <<= 1) {
                uint32_t v = __shfl_xor_sync(0xffffffffu, u, off);
                __half2 r = __hmin2(*(__half2*)&u, *(__half2*)&v);
                u = *(uint32_t*)&r;
            }
            if ((l & 3) == 0) {
                __half2 hv = *(__half2*)&u;
                float smin = fminf(__low2float(hv), __high2float(hv));
                atomicMin(&red_s[wm * 32 + mt * 16 + qr + h * 8], fenc(smin));
            }
        }
    __syncthreads();
    if (tid < 128) {
        float smin = fdec(red_s[tid]);
        float dmin = rI_s[tid] + smin;
        float m = -L2E / (0.5f * (dmin + 1e-5f));
        g_m[n * RP + i0 + tid] = m;
        g_b[n * RP + i0 + tid] = -smin * m;
    }
}

// ---------------- per-row exp-sum kernel (memory-bound) ----------------
__global__ __launch_bounds__(128) void row_kernel() {
    int n = blockIdx.y;
    int r = n * RP + blockIdx.x;          // blockIdx.x < P
    float m = g_m[r], b = g_b[r];
    const uint4* p = (const uint4*)(g_comb + (size_t)r * RP);

    float s = 0.0f;
    #pragma unroll
    for (int it = 0; it < 4; ++it) {
        uint4 v = p[threadIdx.x + it * 128];
        #pragma unroll
        for (int q = 0; q < 4; ++q) {
            unsigned u = (&v.x)[q];
            float2 f = __half22float2(*(__half2*)&u);
            s += ex2f(fmaf(f.x, m, b));
            s += ex2f(fmaf(f.y, m, b));
        }
    }
    // block reduce
    #pragma unroll
    for (int off = 16; off >= 1; off >>= 1)
        s += __shfl_xor_sync(0xffffffffu, s, off);
    __shared__ float red[4];
    if ((threadIdx.x & 31) == 0) red[threadIdx.x >> 5] = s;
    __syncthreads();
    if (threadIdx.x == 0) {
        float t = red[0] + red[1] + red[2] + red[3];
        atomicAdd(&g_acc[n], 1.0f / t);
    }
}

// ---------------- final scalar ----------------
__global__ void final_kernel(float* out) {
    float L = 0.0f;
    #pragma unroll
    for (int n = 0; n < NB; ++n)
        L += -logf(g_acc[n] * (1.0f / (float)P));
    out[0] = L;
}

// ---------------- launch ----------------
extern "C" void kernel_launch(void* const* d_in, const int* in_sizes, int n_in,
                              void* d_out, int out_size) {
    const float* outp = (const float*)d_in[0];
    const float* targ = (const float*)d_in[1];
    float* out = (float*)d_out;

    cudaFuncSetAttribute(main_kernel, cudaFuncAttributeMaxDynamicSharedMemorySize, SMEM_BYTES);

    init_kernel<<<1, 32>>>();
    const int TOT = 2 * NB * RP * KP;
    feat_kernel<<<(TOT + 255) / 256, 256>>>(outp, targ);
    rsq_kernel<<<(2 * NB * RP + 255) / 256, 256>>>();
    main_kernel<<<dim3(NI, NB), 512, SMEM_BYTES>>>();
    row_kernel<<<dim3(P, NB), 128>>>();
    final_kernel<<<1, 1>>>(out);
}

// round 10
// speedup vs baseline: 4.0476x; 1.2349x over previous
#include <cuda_runtime.h>
#include <cuda_bf16.h>
#include <cuda_fp16.h>
#include <math.h>
#include <stdint.h>

// ---------------- problem constants ----------------
#define NB 4
#define HF 63
#define P  3969
#define RP 4096            // rows padded per image
#define KP 80              // 75 feats + 2 coord feats + 3 zero pad
#define NI 32
#define NJ 32
#define IN_H 67
#define CS  0.31622776601683794f   // sqrt(0.1)
#define L2E 1.4426950408889634f

// ---------------- scratch ----------------
__device__ __nv_bfloat16 g_hi[(size_t)2 * NB * RP * KP];
__device__ __nv_bfloat16 g_lo[(size_t)2 * NB * RP * KP];   // only rsq reads this
__device__ float g_r[2 * NB * RP];
__device__ float g_m[NB * RP];
__device__ float g_b[NB * RP];
__device__ __half g_comb[(size_t)NB * RP * RP];   // 134 MB, stores s = rT - 2*dot
__device__ float g_acc[NB];

// ---------------- helpers ----------------
__device__ __forceinline__ uint32_t smem_u32(const void* p) {
    uint32_t a;
    asm("{ .reg .u64 t; cvta.to.shared.u64 t, %1; cvt.u32.u64 %0, t; }" : "=r"(a) : "l"(p));
    return a;
}
__device__ __forceinline__ void cp16(uint32_t dst, const void* src) {
    asm volatile("cp.async.cg.shared.global [%0], [%1], 16;" :: "r"(dst), "l"(src));
}
#define CP_COMMIT() asm volatile("cp.async.commit_group;" ::: "memory")
#define CP_WAIT0()  asm volatile("cp.async.wait_group 0;" ::: "memory")

__device__ __forceinline__ void ldsm4(uint32_t* r, uint32_t addr) {
    asm volatile("ldmatrix.sync.aligned.m8n8.x4.shared.b16 {%0,%1,%2,%3}, [%4];"
        : "=r"(r[0]), "=r"(r[1]), "=r"(r[2]), "=r"(r[3]) : "r"(addr));
}
__device__ __forceinline__ void mma16816(float* d, const uint32_t* a, uint32_t b0, uint32_t b1) {
    asm volatile("mma.sync.aligned.m16n8k16.row.col.f32.bf16.bf16.f32 "
        "{%0,%1,%2,%3},{%4,%5,%6,%7},{%8,%9},{%0,%1,%2,%3};"
        : "+f"(d[0]), "+f"(d[1]), "+f"(d[2]), "+f"(d[3])
        : "r"(a[0]), "r"(a[1]), "r"(a[2]), "r"(a[3]), "r"(b0), "r"(b1));
}
__device__ __forceinline__ float ex2f(float x) {
    float y; asm("ex2.approx.f32 %0, %1;" : "=f"(y) : "f"(x)); return y;
}
__device__ __forceinline__ uint32_t pack_f16x2(float lo, float hi) {
    uint32_t u;
    asm("cvt.rn.f16x2.f32 %0, %1, %2;" : "=r"(u) : "f"(hi), "f"(lo));
    return u;
}
// monotone float<->uint for atomicMin over possibly-negative floats
__device__ __forceinline__ unsigned fenc(float f) {
    int b = __float_as_int(f);
    return (unsigned)(b >= 0 ? (b | 0x80000000) : ~b);
}
__device__ __forceinline__ float fdec(unsigned u) {
    int b = (u & 0x80000000u) ? (int)(u ^ 0x80000000u) : ~(int)u;
    return __int_as_float(b);
}

// ---------------- prep kernels ----------------
__global__ void init_kernel() { if (threadIdx.x < NB) g_acc[threadIdx.x] = 0.0f; }

__global__ void feat_kernel(const float* __restrict__ outp, const float* __restrict__ targ) {
    int idx = blockIdx.x * blockDim.x + threadIdx.x;
    const int TOT = 2 * NB * RP * KP;
    if (idx >= TOT) return;
    int k     = idx % KP;
    int row   = (idx / KP) % RP;
    int n     = (idx / (KP * RP)) % NB;
    int which = idx / (KP * RP * NB);
    float v = 0.0f;
    if (row < P) {
        int y = row / HF, x = row - y * HF;
        if (k < 75) {
            int c = k / 25, t = k - c * 25, dy = t / 5, dx = t - dy * 5;
            const float* src = which ? targ : outp;
            v = src[((n * 3 + c) * IN_H + y + dy) * IN_H + x + dx] - 0.5f;
        } else if (k == 75) v = CS * (float)y * (1.0f / 62.0f);
        else if (k == 76)   v = CS * (float)x * (1.0f / 62.0f);
    }
    __nv_bfloat16 h = __float2bfloat16(v);
    float lo = v - __bfloat162float(h);
    g_hi[idx] = h;
    g_lo[idx] = __float2bfloat16(lo);
}

__global__ void rsq_kernel() {
    int idx = blockIdx.x * blockDim.x + threadIdx.x;
    if (idx >= 2 * NB * RP) return;
    int row   = idx % RP;
    int which = idx / (NB * RP);
    size_t base = (size_t)idx * KP;
    float s = 0.0f;
    #pragma unroll 16
    for (int k = 0; k < KP; ++k) {
        float v = __bfloat162float(g_hi[base + k]) + __bfloat162float(g_lo[base + k]);
        s = fmaf(v, v, s);
    }
    if (which == 1 && row >= P) s = 1e9f;   // T pad rows: s huge -> fp16 inf -> exp 0
    g_r[idx] = s;
}

// ---------------- main GEMM kernel (pure bf16 hh) ----------------
#define TS     176                 // smem row stride (bytes), ldmatrix conflict-free
#define TILE_B (128 * TS)          // 22528
#define SM_RT  0                   // 2 x 128 f
#define SM_RI  1024
#define SM_RED 1536                // encoded uint row-min
#define SM_AH  2048
#define SM_B0  (SM_AH + TILE_B)    // 24576; 2 stages x hi only
#define SMEM_BYTES (SM_B0 + 2 * TILE_B)   // 69632 (68 KB)

__device__ __forceinline__ void load_B_async(uint32_t smB,
                                             const __nv_bfloat16* __restrict__ hi, int tid) {
    for (int t = tid; t < 1280; t += 512) {
        int row = t / 10, c = t - row * 10;
        cp16(smB + row * TS + c * 16, hi + row * KP + c * 8);
    }
}

__global__ __launch_bounds__(512, 1) void main_kernel() {
    extern __shared__ char sm[];
    uint32_t smb = smem_u32(sm);
    int tid = threadIdx.x;
    int w = tid >> 5, l = tid & 31;
    int n  = blockIdx.y;
    int i0 = blockIdx.x * 128;
    int wm = w >> 2, wn = w & 3;

    float*    rT_s  = (float*)(sm + SM_RT);
    float*    rI_s  = (float*)(sm + SM_RI);
    unsigned* red_s = (unsigned*)(sm + SM_RED);

    // ---- load A_hi tile (once) + rI + init min ----
    const __nv_bfloat16* Ahi = g_hi + ((size_t)n * RP + i0) * KP;
    for (int t = tid; t < 1280; t += 512) {
        int row = t / 10, c = t - row * 10;
        *(uint4*)(sm + SM_AH + row * TS + c * 16) = *(const uint4*)(Ahi + row * KP + c * 8);
    }
    if (tid < 128) {
        rI_s[tid]  = g_r[n * RP + i0 + tid];
        red_s[tid] = 0xFFFFFFFFu;
    }
    __syncthreads();

    // ---- per-lane geometry ----
    int qr = l >> 2;
    int qc = (l & 3) * 2;
    int lrow = (l & 7) + ((l >> 3) & 1) * 8;
    int lcol = (l >> 4) * 16;
    int aoff = (wm * 32 + lrow) * TS + lcol;
    int boff = (wn * 32 + lrow) * TS + lcol;

    const __nv_bfloat16* Bhi0 = g_hi + (size_t)(NB + n) * RP * KP;
    const float* rTg = g_r + (NB + n) * RP;

    __half2 hmin[2][2];
    #pragma unroll
    for (int mt = 0; mt < 2; ++mt)
        #pragma unroll
        for (int h = 0; h < 2; ++h)
            hmin[mt][h] = __floats2half2_rn(65504.0f, 65504.0f);

    // base pointer for this CTA's comb rows (u32 granularity; qc even)
    uint32_t* gout = (uint32_t*)(g_comb + ((size_t)n * RP + i0) * RP);

    // preload j=0
    load_B_async(smb + SM_B0, Bhi0, tid);
    CP_COMMIT();
    if (tid < 128) rT_s[tid] = rTg[tid];

    for (int j = 0; j < NJ; ++j) {
        int cur = j & 1;
        CP_WAIT0();
        __syncthreads();               // B[cur] ready; everyone done reading B[cur^1]

        if (j + 1 < NJ) {
            load_B_async(smb + SM_B0 + (cur ^ 1) * TILE_B,
                         Bhi0 + (size_t)(j + 1) * 128 * KP, tid);
            CP_COMMIT();
            if (tid < 128) rT_s[(cur ^ 1) * 128 + tid] = rTg[(j + 1) * 128 + tid];
        }

        // ---- GEMM: pure bf16 hh ----
        float acc[2][4][4];
        #pragma unroll
        for (int mt = 0; mt < 2; ++mt)
            #pragma unroll
            for (int nt = 0; nt < 4; ++nt)
                #pragma unroll
                for (int q = 0; q < 4; ++q) acc[mt][nt][q] = 0.0f;

        uint32_t Bcur = smb + SM_B0 + cur * TILE_B;
        #pragma unroll
        for (int kk = 0; kk < 5; ++kk) {
            uint32_t AH0[4], AH1[4], BH0[4], BH1[4];
            ldsm4(BH0, Bcur + boff + kk * 32);
            ldsm4(BH1, Bcur + boff + 16 * TS + kk * 32);
            ldsm4(AH0, smb + SM_AH + aoff + kk * 32);
            ldsm4(AH1, smb + SM_AH + aoff + 16 * TS + kk * 32);
            mma16816(acc[0][0], AH0, BH0[0], BH0[2]);
            mma16816(acc[0][1], AH0, BH0[1], BH0[3]);
            mma16816(acc[0][2], AH0, BH1[0], BH1[2]);
            mma16816(acc[0][3], AH0, BH1[1], BH1[3]);
            mma16816(acc[1][0], AH1, BH0[0], BH0[2]);
            mma16816(acc[1][1], AH1, BH0[1], BH0[3]);
            mma16816(acc[1][2], AH1, BH1[0], BH1[2]);
            mma16816(acc[1][3], AH1, BH1[1], BH1[3]);
        }

        // ---- epilogue: s = rT - 2*dot, fp16 pack, hmin2 row-min, direct STG ----
        #pragma unroll
        for (int nt = 0; nt < 4; ++nt) {
            float2 rtp = *(const float2*)&rT_s[cur * 128 + wn * 32 + nt * 8 + qc];
            #pragma unroll
            for (int mt = 0; mt < 2; ++mt)
                #pragma unroll
                for (int h = 0; h < 2; ++h) {
                    float s0 = fmaf(-2.0f, acc[mt][nt][2 * h],     rtp.x);
                    float s1 = fmaf(-2.0f, acc[mt][nt][2 * h + 1], rtp.y);
                    uint32_t u = pack_f16x2(s0, s1);
                    hmin[mt][h] = __hmin2(hmin[mt][h], *(__half2*)&u);
                    int srow = wm * 32 + mt * 16 + h * 8 + qr;
                    int scol = wn * 32 + nt * 8 + qc;
                    gout[((size_t)srow * RP + j * 128 + scol) >> 1] = u;
                }
        }
    }

    // ---- row minima -> per-row exp coefficients ----
    #pragma unroll
    for (int mt = 0; mt < 2; ++mt)
        #pragma unroll
        for (int h = 0; h < 2; ++h) {
            uint32_t u = *(uint32_t*)&hmin[mt][h];
            #pragma unroll
            for (int off = 1; off <= 2; off <<= 1) {
                uint32_t v = __shfl_xor_sync(0xffffffffu, u, off);
                __half2 r = __hmin2(*(__half2*)&u, *(__half2*)&v);
                u = *(uint32_t*)&r;
            }
            if ((l & 3) == 0) {
                __half2 hv = *(__half2*)&u;
                float smin = fminf(__low2float(hv), __high2float(hv));
                atomicMin(&red_s[wm * 32 + mt * 16 + qr + h * 8], fenc(smin));
            }
        }
    __syncthreads();
    if (tid < 128) {
        float smin = fdec(red_s[tid]);
        float dmin = rI_s[tid] + smin;
        float m = -L2E / (0.5f * (dmin + 1e-5f));
        g_m[n * RP + i0 + tid] = m;
        g_b[n * RP + i0 + tid] = -smin * m;
    }
}

// ---------------- per-row exp-sum kernel (memory-bound) ----------------
__global__ __launch_bounds__(128) void row_kernel() {
    int n = blockIdx.y;
    int r = n * RP + blockIdx.x;          // blockIdx.x < P
    float m = g_m[r], b = g_b[r];
    const uint4* p = (const uint4*)(g_comb + (size_t)r * RP);

    float s = 0.0f;
    #pragma unroll
    for (int it = 0; it < 4; ++it) {
        uint4 v = p[threadIdx.x + it * 128];
        #pragma unroll
        for (int q = 0; q < 4; ++q) {
            unsigned u = (&v.x)[q];
            float2 f = __half22float2(*(__half2*)&u);
            s += ex2f(fmaf(f.x, m, b));
            s += ex2f(fmaf(f.y, m, b));
        }
    }
    // block reduce
    #pragma unroll
    for (int off = 16; off >= 1; off >>= 1)
        s += __shfl_xor_sync(0xffffffffu, s, off);
    __shared__ float red[4];
    if ((threadIdx.x & 31) == 0) red[threadIdx.x >> 5] = s;
    __syncthreads();
    if (threadIdx.x == 0) {
        float t = red[0] + red[1] + red[2] + red[3];
        atomicAdd(&g_acc[n], 1.0f / t);
    }
}

// ---------------- final scalar ----------------
__global__ void final_kernel(float* out) {
    float L = 0.0f;
    #pragma unroll
    for (int n = 0; n < NB; ++n)
        L += -logf(g_acc[n] * (1.0f / (float)P));
    out[0] = L;
}

// ---------------- launch ----------------
extern "C" void kernel_launch(void* const* d_in, const int* in_sizes, int n_in,
                              void* d_out, int out_size) {
    const float* outp = (const float*)d_in[0];
    const float* targ = (const float*)d_in[1];
    float* out = (float*)d_out;

    cudaFuncSetAttribute(main_kernel, cudaFuncAttributeMaxDynamicSharedMemorySize, SMEM_BYTES);

    init_kernel<<<1, 32>>>();
    const int TOT = 2 * NB * RP * KP;
    feat_kernel<<<(TOT + 255) / 256, 256>>>(outp, targ);
    rsq_kernel<<<(2 * NB * RP + 255) / 256, 256>>>();
    main_kernel<<<dim3(NI, NB), 512, SMEM_BYTES>>>();
    row_kernel<<<dim3(P, NB), 128>>>();
    final_kernel<<<1, 1>>>(out);
}

// round 11
// speedup vs baseline: 4.4737x; 1.1053x over previous
#include <cuda_runtime.h>
#include <cuda_bf16.h>
#include <cuda_fp16.h>
#include <math.h>
#include <stdint.h>

// ---------------- problem constants ----------------
#define NB 4
#define HF 63
#define P  3969
#define RP 4096            // rows padded per image
#define KP 80              // 75 feats + 2 coord feats + 3 zero pad
#define NI 32
#define NJH 2              // j halves
#define NJT 16             // j tiles per half
#define IN_H 67
#define CS  0.31622776601683794f   // sqrt(0.1)
#define L2E 1.4426950408889634f

// ---------------- scratch ----------------
__device__ __nv_bfloat16 g_hi[(size_t)2 * NB * RP * KP];
__device__ float    g_r[2 * NB * RP];
__device__ unsigned g_dmin[NB * RP];
__device__ float    g_m[NB * RP];
__device__ float    g_b[NB * RP];
__device__ __half   g_comb[(size_t)NB * RP * RP];   // 134 MB, stores s = rT - 2*dot
__device__ float    g_acc[NB];

// ---------------- helpers ----------------
__device__ __forceinline__ uint32_t smem_u32(const void* p) {
    uint32_t a;
    asm("{ .reg .u64 t; cvta.to.shared.u64 t, %1; cvt.u32.u64 %0, t; }" : "=r"(a) : "l"(p));
    return a;
}
__device__ __forceinline__ void cp16(uint32_t dst, const void* src) {
    asm volatile("cp.async.cg.shared.global [%0], [%1], 16;" :: "r"(dst), "l"(src));
}
#define CP_COMMIT() asm volatile("cp.async.commit_group;" ::: "memory")
#define CP_WAIT0()  asm volatile("cp.async.wait_group 0;" ::: "memory")

__device__ __forceinline__ void ldsm4(uint32_t* r, uint32_t addr) {
    asm volatile("ldmatrix.sync.aligned.m8n8.x4.shared.b16 {%0,%1,%2,%3}, [%4];"
        : "=r"(r[0]), "=r"(r[1]), "=r"(r[2]), "=r"(r[3]) : "r"(addr));
}
__device__ __forceinline__ void mma16816(float* d, const uint32_t* a, uint32_t b0, uint32_t b1) {
    asm volatile("mma.sync.aligned.m16n8k16.row.col.f32.bf16.bf16.f32 "
        "{%0,%1,%2,%3},{%4,%5,%6,%7},{%8,%9},{%0,%1,%2,%3};"
        : "+f"(d[0]), "+f"(d[1]), "+f"(d[2]), "+f"(d[3])
        : "r"(a[0]), "r"(a[1]), "r"(a[2]), "r"(a[3]), "r"(b0), "r"(b1));
}
__device__ __forceinline__ float ex2f(float x) {
    float y; asm("ex2.approx.f32 %0, %1;" : "=f"(y) : "f"(x)); return y;
}
__device__ __forceinline__ uint32_t pack_f16x2(float lo, float hi) {
    uint32_t u;
    asm("cvt.rn.f16x2.f32 %0, %1, %2;" : "=r"(u) : "f"(hi), "f"(lo));
    return u;
}
// monotone float<->uint for atomicMin over possibly-negative floats
__device__ __forceinline__ unsigned fenc(float f) {
    int b = __float_as_int(f);
    return (unsigned)(b >= 0 ? (b | 0x80000000) : ~b);
}
__device__ __forceinline__ float fdec(unsigned u) {
    int b = (u & 0x80000000u) ? (int)(u ^ 0x80000000u) : ~(int)u;
    return __int_as_float(b);
}

// ---------------- prep kernels ----------------
__global__ void init_kernel() {
    int idx = blockIdx.x * blockDim.x + threadIdx.x;
    if (idx < NB * RP) g_dmin[idx] = 0xFFFFFFFFu;
    if (idx < NB)      g_acc[idx] = 0.0f;
}

// one warp per (which, n, row): writes bf16 features + row sum of squares
__global__ __launch_bounds__(256) void featrsq_kernel(const float* __restrict__ outp,
                                                      const float* __restrict__ targ) {
    int gw = (blockIdx.x * blockDim.x + threadIdx.x) >> 5;
    int l  = threadIdx.x & 31;
    if (gw >= 2 * NB * RP) return;
    int row   = gw % RP;
    int n     = (gw / RP) % NB;
    int which = gw / (RP * NB);

    __nv_bfloat16* dst = g_hi + (size_t)gw * KP;
    const float* src = which ? targ : outp;
    int y = row / HF, x = row - y * HF;
    bool valid = (row < P);

    float sum = 0.0f;
    #pragma unroll
    for (int k = l; k < KP; k += 32) {
        float v = 0.0f;
        if (valid) {
            if (k < 75) {
                int c = k / 25, t = k - c * 25, dy = t / 5, dx = t - dy * 5;
                v = src[((n * 3 + c) * IN_H + y + dy) * IN_H + x + dx] - 0.5f;
            } else if (k == 75) v = CS * (float)y * (1.0f / 62.0f);
            else if (k == 76)   v = CS * (float)x * (1.0f / 62.0f);
        }
        dst[k] = __float2bfloat16(v);
        sum = fmaf(v, v, sum);
    }
    #pragma unroll
    for (int off = 16; off >= 1; off >>= 1)
        sum += __shfl_xor_sync(0xffffffffu, sum, off);
    if (l == 0) {
        if (which == 1 && row >= P) sum = 1e9f;   // T pad rows: s huge -> fp16 inf -> exp 0
        g_r[gw] = sum;
    }
}

// ---------------- main GEMM kernel (pure bf16 hh, 256 thr, warp tile 32x64) ----------------
#define TS     176                 // smem row stride (bytes), ldmatrix conflict-free
#define TILE_B (128 * TS)          // 22528
#define SM_RT  0                   // 2 x 128 f
#define SM_RED 1024                // encoded uint row-min (128)
#define SM_AH  2048
#define SM_B0  (SM_AH + TILE_B)    // 24576; 2 stages
#define SMEM_BYTES (SM_B0 + 2 * TILE_B)   // 69632 (68 KB)

__device__ __forceinline__ void load_B_async(uint32_t smB,
                                             const __nv_bfloat16* __restrict__ hi, int tid) {
    for (int t = tid; t < 1280; t += 256) {
        int row = t / 10, c = t - row * 10;
        cp16(smB + row * TS + c * 16, hi + row * KP + c * 8);
    }
}

__global__ __launch_bounds__(256, 2) void main_kernel() {
    extern __shared__ char sm[];
    uint32_t smb = smem_u32(sm);
    int tid = threadIdx.x;
    int w = tid >> 5, l = tid & 31;
    int n  = blockIdx.z;
    int i0 = blockIdx.x * 128;
    int jh = blockIdx.y;
    int wm = w >> 1, wn = w & 1;        // 4 x 2 warp grid, warp tile 32 x 64

    float*    rT_s  = (float*)(sm + SM_RT);
    unsigned* red_s = (unsigned*)(sm + SM_RED);

    // ---- load A_hi tile (once) + init min ----
    const __nv_bfloat16* Ahi = g_hi + ((size_t)n * RP + i0) * KP;
    for (int t = tid; t < 1280; t += 256) {
        int row = t / 10, c = t - row * 10;
        *(uint4*)(sm + SM_AH + row * TS + c * 16) = *(const uint4*)(Ahi + row * KP + c * 8);
    }
    if (tid < 128) red_s[tid] = 0xFFFFFFFFu;
    __syncthreads();

    // ---- per-lane geometry ----
    int qr = l >> 2;
    int qc = (l & 3) * 2;
    int lrow = (l & 7) + ((l >> 3) & 1) * 8;
    int lcol = (l >> 4) * 16;
    int aoff = (wm * 32 + lrow) * TS + lcol;
    int boff = (wn * 64 + lrow) * TS + lcol;

    const __nv_bfloat16* Bhi0 = g_hi + ((size_t)(NB + n) * RP + jh * (NJT * 128)) * KP;
    const float* rTg = g_r + (NB + n) * RP + jh * (NJT * 128);

    __half2 hmin[2][2];
    #pragma unroll
    for (int mt = 0; mt < 2; ++mt)
        #pragma unroll
        for (int h = 0; h < 2; ++h)
            hmin[mt][h] = __floats2half2_rn(65504.0f, 65504.0f);

    // base pointer for this CTA's comb region (u32 granularity; qc even)
    uint32_t* gout = (uint32_t*)(g_comb + ((size_t)n * RP + i0) * RP + jh * (NJT * 128));

    // preload j=0
    load_B_async(smb + SM_B0, Bhi0, tid);
    CP_COMMIT();
    if (tid < 128) rT_s[tid] = rTg[tid];

    for (int j = 0; j < NJT; ++j) {
        int cur = j & 1;
        CP_WAIT0();
        __syncthreads();               // B[cur] ready; everyone done reading B[cur^1]

        if (j + 1 < NJT) {
            load_B_async(smb + SM_B0 + (cur ^ 1) * TILE_B,
                         Bhi0 + (size_t)(j + 1) * 128 * KP, tid);
            CP_COMMIT();
            if (tid < 128) rT_s[(cur ^ 1) * 128 + tid] = rTg[(j + 1) * 128 + tid];
        }

        // ---- GEMM: pure bf16 hh, 32x64 warp tile ----
        float acc[2][8][4];
        #pragma unroll
        for (int mt = 0; mt < 2; ++mt)
            #pragma unroll
            for (int nt = 0; nt < 8; ++nt)
                #pragma unroll
                for (int q = 0; q < 4; ++q) acc[mt][nt][q] = 0.0f;

        uint32_t Bcur = smb + SM_B0 + cur * TILE_B;
        #pragma unroll
        for (int kk = 0; kk < 5; ++kk) {
            uint32_t AH0[4], AH1[4], BF[4][4];
            ldsm4(AH0, smb + SM_AH + aoff + kk * 32);
            ldsm4(AH1, smb + SM_AH + aoff + 16 * TS + kk * 32);
            #pragma unroll
            for (int f = 0; f < 4; ++f)
                ldsm4(BF[f], Bcur + boff + f * 16 * TS + kk * 32);
            #pragma unroll
            for (int f = 0; f < 4; ++f) {
                mma16816(acc[0][2 * f],     AH0, BF[f][0], BF[f][2]);
                mma16816(acc[0][2 * f + 1], AH0, BF[f][1], BF[f][3]);
                mma16816(acc[1][2 * f],     AH1, BF[f][0], BF[f][2]);
                mma16816(acc[1][2 * f + 1], AH1, BF[f][1], BF[f][3]);
            }
        }

        // ---- epilogue: s = rT - 2*dot, fp16 pack, hmin2 row-min, direct STG ----
        #pragma unroll
        for (int nt = 0; nt < 8; ++nt) {
            float2 rtp = *(const float2*)&rT_s[cur * 128 + wn * 64 + nt * 8 + qc];
            #pragma unroll
            for (int mt = 0; mt < 2; ++mt)
                #pragma unroll
                for (int h = 0; h < 2; ++h) {
                    float s0 = fmaf(-2.0f, acc[mt][nt][2 * h],     rtp.x);
                    float s1 = fmaf(-2.0f, acc[mt][nt][2 * h + 1], rtp.y);
                    uint32_t u = pack_f16x2(s0, s1);
                    hmin[mt][h] = __hmin2(hmin[mt][h], *(__half2*)&u);
                    int srow = wm * 32 + mt * 16 + h * 8 + qr;
                    int scol = wn * 64 + nt * 8 + qc;
                    gout[((size_t)srow * RP + j * 128 + scol) >> 1] = u;
                }
        }
    }

    // ---- row minima: quad -> shared -> global ----
    #pragma unroll
    for (int mt = 0; mt < 2; ++mt)
        #pragma unroll
        for (int h = 0; h < 2; ++h) {
            uint32_t u = *(uint32_t*)&hmin[mt][h];
            #pragma unroll
            for (int off = 1; off <= 2; off <<= 1) {
                uint32_t v = __shfl_xor_sync(0xffffffffu, u, off);
                __half2 r = __hmin2(*(__half2*)&u, *(__half2*)&v);
                u = *(uint32_t*)&r;
            }
            if ((l & 3) == 0) {
                __half2 hv = *(__half2*)&u;
                float smin = fminf(__low2float(hv), __high2float(hv));
                atomicMin(&red_s[wm * 32 + mt * 16 + qr + h * 8], fenc(smin));
            }
        }
    __syncthreads();
    if (tid < 128) atomicMin(&g_dmin[n * RP + i0 + tid], red_s[tid]);
}

// ---------------- per-row exp coefficients ----------------
__global__ void mb_kernel() {
    int idx = blockIdx.x * blockDim.x + threadIdx.x;
    if (idx >= NB * RP) return;
    float smin = fdec(g_dmin[idx]);
    float dmin = g_r[idx] + smin;       // g_r first half = rI
    float m = -L2E / (0.5f * (dmin + 1e-5f));
    g_m[idx] = m;
    g_b[idx] = -smin * m;
}

// ---------------- per-row exp-sum kernel (memory-bound) ----------------
__global__ __launch_bounds__(128) void row_kernel() {
    int n = blockIdx.y;
    int r = n * RP + blockIdx.x;          // blockIdx.x < P
    float m = g_m[r], b = g_b[r];
    const uint4* p = (const uint4*)(g_comb + (size_t)r * RP);

    float s = 0.0f;
    #pragma unroll
    for (int it = 0; it < 4; ++it) {
        uint4 v = p[threadIdx.x + it * 128];
        #pragma unroll
        for (int q = 0; q < 4; ++q) {
            unsigned u = (&v.x)[q];
            float2 f = __half22float2(*(__half2*)&u);
            s += ex2f(fmaf(f.x, m, b));
            s += ex2f(fmaf(f.y, m, b));
        }
    }
    #pragma unroll
    for (int off = 16; off >= 1; off >>= 1)
        s += __shfl_xor_sync(0xffffffffu, s, off);
    __shared__ float red[4];
    if ((threadIdx.x & 31) == 0) red[threadIdx.x >> 5] = s;
    __syncthreads();
    if (threadIdx.x == 0) {
        float t = red[0] + red[1] + red[2] + red[3];
        atomicAdd(&g_acc[n], 1.0f / t);
    }
}

// ---------------- final scalar ----------------
__global__ void final_kernel(float* out) {
    float L = 0.0f;
    #pragma unroll
    for (int n = 0; n < NB; ++n)
        L += -logf(g_acc[n] * (1.0f / (float)P));
    out[0] = L;
}

// ---------------- launch ----------------
extern "C" void kernel_launch(void* const* d_in, const int* in_sizes, int n_in,
                              void* d_out, int out_size) {
    const float* outp = (const float*)d_in[0];
    const float* targ = (const float*)d_in[1];
    float* out = (float*)d_out;

    cudaFuncSetAttribute(main_kernel, cudaFuncAttributeMaxDynamicSharedMemorySize, SMEM_BYTES);

    init_kernel<<<(NB * RP + 255) / 256, 256>>>();
    featrsq_kernel<<<(2 * NB * RP) / 8, 256>>>(outp, targ);
    main_kernel<<<dim3(NI, NJH, NB), 256, SMEM_BYTES>>>();
    mb_kernel<<<(NB * RP + 255) / 256, 256>>>();
    row_kernel<<<dim3(P, NB), 128>>>();
    final_kernel<<<1, 1>>>(out);
}